// round 11
// baseline (speedup 1.0000x reference)
#include <cuda_runtime.h>
#include <math.h>

#define NN 768
#define HH 12
#define SQKd 16
#define SVd 16
#define PQKd 4
#define PVd 8
#define C1d 384
#define C2d 128
#define CONCAT 2112   // H*(SV + 4*PV + C2) = 12*176
#define NPROJ 1152    // 192*3 + 144*2 + 288

// -------- scratch (device globals; no allocation allowed) --------
__device__ __align__(16) float g_wcat[C1d*NPROJ];
__device__ __align__(16) float g_bcat[NPROJ];
__device__ __align__(16) float g_proj[NN*NPROJ];
__device__ __align__(16) float g_q  [NN*HH*SQKd];
__device__ __align__(16) float g_k  [NN*HH*SQKd];
__device__ __align__(16) float g_vh [HH*NN*SVd];
__device__ __align__(16) float g_qp [NN*HH*PQKd*3];
__device__ __align__(16) float g_kp [NN*HH*PQKd*3];
__device__ __align__(16) float g_vph[HH*NN*PVd*3];
__device__ __align__(16) float g_sq [NN*HH];
__device__ __align__(16) float g_sk [NN*HH];
__device__ __align__(16) float g_attn[(size_t)NN*HH*NN]; // [q][h][k]
__device__ __align__(16) float g_rpg[NN*HH*PVd*3];
__device__ __align__(16) float g_cbuf[NN*CONCAT];

// -------- f32x2 packed math helpers --------
typedef unsigned long long ull;
__device__ __forceinline__ ull pack2(float x, float y) {
    ull r; asm("mov.b64 %0, {%1, %2};" : "=l"(r) : "f"(x), "f"(y)); return r;
}
__device__ __forceinline__ float2 unpack2(ull v) {
    float2 r; asm("mov.b64 {%0, %1}, %2;" : "=f"(r.x), "=f"(r.y) : "l"(v)); return r;
}
__device__ __forceinline__ ull ffma2(ull a, ull b, ull c) {
    ull d; asm("fma.rn.f32x2 %0, %1, %2, %3;" : "=l"(d) : "l"(a), "l"(b), "l"(c)); return d;
}
__device__ __forceinline__ ull add2(ull a, ull b) {
    ull d; asm("add.rn.f32x2 %0, %1, %2;" : "=l"(d) : "l"(a), "l"(b)); return d;
}

// fast exp: 2^(x*log2e), range-reduced, degree-4 poly on FMA pipe.
__device__ __forceinline__ float fast_exp(float x) {
    float y = x * 1.44269504089f;
    y = fmaxf(y, -126.0f);
    float i = rintf(y);
    float f = y - i;
    float p = 0.00961804886f;
    p = fmaf(p, f, 0.05550410866f);
    p = fmaf(p, f, 0.24022650696f);
    p = fmaf(p, f, 0.69314718056f);
    p = fmaf(p, f, 1.0f);
    float s = __int_as_float(((int)i + 127) << 23);
    return p * s;
}

// =====================================================================
// KP: pack projection weights into one concat matrix [384 x 1152] + bias
// =====================================================================
__global__ void kpack(const float* __restrict__ wq, const float* __restrict__ wk,
                      const float* __restrict__ wv,
                      const float* __restrict__ wqp, const float* __restrict__ bqp,
                      const float* __restrict__ wkp, const float* __restrict__ bkp,
                      const float* __restrict__ wvp, const float* __restrict__ bvp) {
    int idx = blockIdx.x*256 + threadIdx.x;
    if (idx >= C1d*NPROJ) return;
    int c = idx / NPROJ, col = idx % NPROJ;
    float v;
    if (col < 192)      v = wq [c*192 + col];
    else if (col < 384) v = wk [c*192 + col-192];
    else if (col < 576) v = wv [c*192 + col-384];
    else if (col < 720) v = wqp[c*144 + col-576];
    else if (col < 864) v = wkp[c*144 + col-720];
    else                v = wvp[c*288 + col-864];
    g_wcat[idx] = v;
    if (c == 0) {
        float b = 0.f;
        if (col >= 576 && col < 720) b = bqp[col-576];
        else if (col >= 720 && col < 864) b = bkp[col-720];
        else if (col >= 864) b = bvp[col-864];
        g_bcat[col] = b;
    }
}

// =====================================================================
// gemm128: C[M,N] = A[M,K] @ B[K,N] + bias[N]. Tile 32m x 64n, kc=16.
// 128 threads, 4x4 micro-tile, LDS.128 operands. 2 LDS : 8 FFMA2 per kk.
// =====================================================================
__global__ void __launch_bounds__(128) gemm128(
        const float* __restrict__ A, const float* __restrict__ B,
        const float* __restrict__ bias, float* __restrict__ C,
        int K, int N) {
    __shared__ float sAT[16][36];
    __shared__ float sB[16][68];
    int m0 = blockIdx.x * 32, n0 = blockIdx.y * 64;
    int tid = threadIdx.x;
    int tx = tid & 15, ty = tid >> 4;   // tx: n-quad (0..15), ty: m-quad (0..7)
    ull acc[4][2];
    ull z = pack2(0.f, 0.f);
    #pragma unroll
    for (int i = 0; i < 4; i++) { acc[i][0] = z; acc[i][1] = z; }

    for (int k0 = 0; k0 < K; k0 += 16) {
        {   // A: 32 rows x 16 k, transposed
            int row = tid >> 2, cp = (tid & 3) * 4;
            float4 a = *(const float4*)(A + (size_t)(m0+row)*K + k0 + cp);
            sAT[cp+0][row]=a.x; sAT[cp+1][row]=a.y; sAT[cp+2][row]=a.z; sAT[cp+3][row]=a.w;
        }
        {   // B: 16 rows x 64 n
            int r = tid >> 3, c = (tid & 7) * 8;
            float4 b0 = *(const float4*)(B + (size_t)(k0+r)*N + n0 + c);
            float4 b1 = *(const float4*)(B + (size_t)(k0+r)*N + n0 + c + 4);
            sB[r][c+0]=b0.x; sB[r][c+1]=b0.y; sB[r][c+2]=b0.z; sB[r][c+3]=b0.w;
            sB[r][c+4]=b1.x; sB[r][c+5]=b1.y; sB[r][c+6]=b1.z; sB[r][c+7]=b1.w;
        }
        __syncthreads();
        #pragma unroll
        for (int kk = 0; kk < 16; kk++) {
            float4 a = *(const float4*)&sAT[kk][ty*4];
            ulonglong2 b = *(const ulonglong2*)&sB[kk][tx*4];
            float av[4] = {a.x, a.y, a.z, a.w};
            #pragma unroll
            for (int i = 0; i < 4; i++) {
                ull a2 = pack2(av[i], av[i]);
                acc[i][0] = ffma2(a2, b.x, acc[i][0]);
                acc[i][1] = ffma2(a2, b.y, acc[i][1]);
            }
        }
        __syncthreads();
    }
    #pragma unroll
    for (int i = 0; i < 4; i++) {
        float2 v0 = unpack2(acc[i][0]);
        float2 v1 = unpack2(acc[i][1]);
        float* dst = C + (size_t)(m0+ty*4+i)*N + n0 + tx*4;
        dst[0] = v0.x + bias[n0+tx*4+0];
        dst[1] = v0.y + bias[n0+tx*4+1];
        dst[2] = v1.x + bias[n0+tx*4+2];
        dst[3] = v1.y + bias[n0+tx*4+3];
    }
}

// =====================================================================
// K1b: scatter q/k/v, apply rigid frames to points, compute sq/sk.
// =====================================================================
__global__ void k1b(const float* __restrict__ rot, const float* __restrict__ trans) {
    int n = blockIdx.x;
    int tid = threadIdx.x; // 576
    __shared__ float s_p[NPROJ];
    __shared__ float s_app[96*3];
    __shared__ float s_rot[9], s_tr[3];
    for (int i = tid; i < NPROJ; i += 576) s_p[i] = g_proj[(size_t)n*NPROJ + i];
    if (tid < 9) s_rot[tid] = rot[n*9 + tid];
    if (tid < 3) s_tr[tid]  = trans[n*3 + tid];
    __syncthreads();

    if (tid < 192)      g_q[n*192 + tid] = s_p[tid] * 0.25f;
    else if (tid < 384) { int o = tid-192; g_k[n*192 + o] = s_p[192 + o]; }
    else { int o = tid-384; g_vh[(o >> 4)*(NN*SVd) + n*SVd + (o & 15)] = s_p[384 + o]; }

    const float* raw = s_p + 576;
    if (tid < 192) {
        float l0, l1, l2;
        if (tid < 48) {
            int h = tid >> 2, p = tid & 3;
            l0 = raw[h*12 + p]; l1 = raw[h*12 + 4 + p]; l2 = raw[h*12 + 8 + p];
        } else if (tid < 96) {
            int j = tid - 48; int h = j >> 2, p = j & 3;
            l0 = raw[144 + h*12 + p]; l1 = raw[144 + h*12 + 4 + p]; l2 = raw[144 + h*12 + 8 + p];
        } else {
            int j = tid - 96; int h = j >> 3, p = j & 7;
            l0 = raw[288 + h*24 + p]; l1 = raw[288 + h*24 + 8 + p]; l2 = raw[288 + h*24 + 16 + p];
        }
        float gx = s_rot[0]*l0 + s_rot[1]*l1 + s_rot[2]*l2 + s_tr[0];
        float gy = s_rot[3]*l0 + s_rot[4]*l1 + s_rot[5]*l2 + s_tr[1];
        float gz = s_rot[6]*l0 + s_rot[7]*l1 + s_rot[8]*l2 + s_tr[2];
        if (tid < 48) {
            g_qp[n*144 + tid*3+0] = gx; g_qp[n*144 + tid*3+1] = gy; g_qp[n*144 + tid*3+2] = gz;
            s_app[tid*3+0] = gx; s_app[tid*3+1] = gy; s_app[tid*3+2] = gz;
        } else if (tid < 96) {
            int j = tid - 48;
            g_kp[n*144 + j*3+0] = gx; g_kp[n*144 + j*3+1] = gy; g_kp[n*144 + j*3+2] = gz;
            s_app[tid*3+0] = gx; s_app[tid*3+1] = gy; s_app[tid*3+2] = gz;
        } else {
            int j = tid - 96; int h = j >> 3, p = j & 7;
            g_vph[h*(NN*PVd*3) + n*(PVd*3) + p*3+0] = gx;
            g_vph[h*(NN*PVd*3) + n*(PVd*3) + p*3+1] = gy;
            g_vph[h*(NN*PVd*3) + n*(PVd*3) + p*3+2] = gz;
        }
    }
    __syncthreads();
    if (tid < 24) {
        int h = tid % 12;
        int base = (tid < 12) ? 0 : 144;
        float s = 0.f;
        #pragma unroll
        for (int p = 0; p < 4; p++) {
            float x = s_app[base + (h*4+p)*3+0];
            float y = s_app[base + (h*4+p)*3+1];
            float z = s_app[base + (h*4+p)*3+2];
            s += x*x + y*y + z*z;
        }
        if (tid < 12) g_sq[n*12 + h] = s; else g_sk[n*12 + h] = s;
    }
}

// =====================================================================
// K2a v5: Z = act2d @ w2d + b2d -> g_attn[q][h][k].
// Grid (q, 256-k chunk) = 2304 blocks, 128 threads, 2 k per thread.
// 16-channel chunks: smem 23.4KB -> 8 blocks/SM (launch_bounds 128,8).
// =====================================================================
__global__ void __launch_bounds__(128, 8) k2a(
        const float* __restrict__ act2d,
        const float* __restrict__ w2d,
        const float* __restrict__ b2d) {
    __shared__ float s_a[256][17];
    __shared__ ull s_w[128][6];
    int tid = threadIdx.x;  // 128
    int q = blockIdx.x / 3, k0 = (blockIdx.x % 3) * 256;

    for (int i = tid; i < 768; i += 128) {
        int c = i / 6, hh = i % 6;
        s_w[c][hh] = pack2(w2d[c*12 + hh*2], w2d[c*12 + hh*2 + 1]);
    }
    ull acc[2][6];
    #pragma unroll
    for (int hh = 0; hh < 6; hh++) {
        ull b = pack2(b2d[2*hh], b2d[2*hh+1]);
        acc[0][hh] = b; acc[1][hh] = b;
    }

    const float* base = act2d + ((size_t)q*NN + k0)*C2d;
    for (int c0 = 0; c0 < 128; c0 += 16) {
        __syncthreads();
        // stage 256 rows x 16 channels: 1024 float4, coalesced (4 thr/row)
        #pragma unroll
        for (int it = 0; it < 8; it++) {
            int i = it*128 + tid;
            int r = i >> 2, c4 = i & 3;
            float4 v = *(const float4*)(base + (size_t)r*C2d + c0 + c4*4);
            s_a[r][c4*4+0] = v.x; s_a[r][c4*4+1] = v.y;
            s_a[r][c4*4+2] = v.z; s_a[r][c4*4+3] = v.w;
        }
        __syncthreads();
        #pragma unroll
        for (int c = 0; c < 16; c++) {
            float a0 = s_a[tid][c];
            float a1 = s_a[tid+128][c];
            const ull* wr = s_w[c0 + c];
            ulonglong2 w01 = *(const ulonglong2*)(wr);
            ulonglong2 w23 = *(const ulonglong2*)(wr+2);
            ulonglong2 w45 = *(const ulonglong2*)(wr+4);
            ull p0 = pack2(a0, a0);
            ull p1 = pack2(a1, a1);
            acc[0][0] = ffma2(p0, w01.x, acc[0][0]);
            acc[0][1] = ffma2(p0, w01.y, acc[0][1]);
            acc[0][2] = ffma2(p0, w23.x, acc[0][2]);
            acc[0][3] = ffma2(p0, w23.y, acc[0][3]);
            acc[0][4] = ffma2(p0, w45.x, acc[0][4]);
            acc[0][5] = ffma2(p0, w45.y, acc[0][5]);
            acc[1][0] = ffma2(p1, w01.x, acc[1][0]);
            acc[1][1] = ffma2(p1, w01.y, acc[1][1]);
            acc[1][2] = ffma2(p1, w23.x, acc[1][2]);
            acc[1][3] = ffma2(p1, w23.y, acc[1][3]);
            acc[1][4] = ffma2(p1, w45.x, acc[1][4]);
            acc[1][5] = ffma2(p1, w45.y, acc[1][5]);
        }
    }
    #pragma unroll
    for (int kk = 0; kk < 2; kk++) {
        float* dst = g_attn + (size_t)q*(HH*NN) + k0 + kk*128 + tid;
        #pragma unroll
        for (int hh = 0; hh < 6; hh++) {
            float2 v = unpack2(acc[kk][hh]);
            dst[(size_t)(2*hh)*NN]   = v.x;
            dst[(size_t)(2*hh+1)*NN] = v.y;
        }
    }
}

// =====================================================================
// K2b: add qk-dot + point-distance + mask terms, scale. Per head.
// =====================================================================
__global__ void k2b(const float* __restrict__ smask, const float* __restrict__ tw) {
    int k0 = blockIdx.x * 192, q0 = blockIdx.y * 64, h = blockIdx.z;
    int tid = threadIdx.x;
    __shared__ float s_qc[64][28];
    __shared__ float s_kc[28][192];
    __shared__ float s_sq[64], s_sk[192], s_mq[64], s_mk[192];
    float pw = 0.23570226039f * log1pf(expf(tw[h]));

    for (int i = tid; i < 64*16;  i += 256) { int r=i>>4, c=i&15;  s_qc[r][c]    = g_q [(q0+r)*192 + h*16 + c]; }
    for (int i = tid; i < 64*12;  i += 256) { int r=i/12, c=i%12;  s_qc[r][16+c] = pw * g_qp[(q0+r)*144 + h*12 + c]; }
    for (int i = tid; i < 192*16; i += 256) { int kk=i>>4, c=i&15; s_kc[c][kk]    = g_k [(k0+kk)*192 + h*16 + c]; }
    for (int i = tid; i < 192*12; i += 256) { int kk=i/12, c=i%12; s_kc[16+c][kk] = g_kp[(k0+kk)*144 + h*12 + c]; }
    if (tid < 64)  { s_sq[tid] = g_sq[(q0+tid)*12 + h]; s_mq[tid] = smask[q0+tid]; }
    if (tid < 192) { s_sk[tid] = g_sk[(k0+tid)*12 + h]; s_mk[tid] = smask[k0+tid]; }
    __syncthreads();

    int tc = tid & 31, tr = tid >> 5;
    ull acc2[8][3];
    ull z = pack2(0.f, 0.f);
    #pragma unroll
    for (int i = 0; i < 8; i++) { acc2[i][0]=z; acc2[i][1]=z; acc2[i][2]=z; }

    #pragma unroll 4
    for (int c = 0; c < 28; c++) {
        const float* kr = &s_kc[c][tc];
        ull b2[3];
        #pragma unroll
        for (int jp = 0; jp < 3; jp++) b2[jp] = pack2(kr[32*(2*jp)], kr[32*(2*jp+1)]);
        #pragma unroll
        for (int i = 0; i < 8; i++) {
            float a = s_qc[tr*8+i][c];
            ull a2 = pack2(a, a);
            acc2[i][0] = ffma2(a2, b2[0], acc2[i][0]);
            acc2[i][1] = ffma2(a2, b2[1], acc2[i][1]);
            acc2[i][2] = ffma2(a2, b2[2], acc2[i][2]);
        }
    }
    #pragma unroll
    for (int i = 0; i < 8; i++) {
        int q = q0 + tr*8 + i;
        float sqv = s_sq[tr*8+i], mq = s_mq[tr*8+i];
        float* row = g_attn + (size_t)q*(HH*NN) + h*NN + k0 + tc;
        #pragma unroll
        for (int jp = 0; jp < 3; jp++) {
            float2 v = unpack2(acc2[i][jp]);
            int j0 = 32*(2*jp), j1 = 32*(2*jp+1);
            float l0 = row[j0] + v.x - 0.5f*pw*(sqv + s_sk[tc+j0]) - 1e5f*(1.f - mq*s_mk[tc+j0]);
            float l1 = row[j1] + v.y - 0.5f*pw*(sqv + s_sk[tc+j1]) - 1e5f*(1.f - mq*s_mk[tc+j1]);
            row[j0] = l0 * 0.57735026919f;
            row[j1] = l1 * 0.57735026919f;
        }
    }
}

// =====================================================================
// K3: softmax over keys. 9216 rows of 768, poly exp on FMA pipe.
// =====================================================================
__global__ void k3_softmax() {
    int r = blockIdx.x;
    float* row = g_attn + (size_t)r*NN;
    int tid = threadIdx.x;
    float v0 = row[tid], v1 = row[tid+256], v2 = row[tid+512];
    float m = fmaxf(fmaxf(v0, v1), v2);
    __shared__ float sred[8];
    #pragma unroll
    for (int o = 16; o; o >>= 1) m = fmaxf(m, __shfl_xor_sync(0xffffffffu, m, o));
    if ((tid & 31) == 0) sred[tid >> 5] = m;
    __syncthreads();
    float mm = sred[0];
    #pragma unroll
    for (int i = 1; i < 8; i++) mm = fmaxf(mm, sred[i]);
    float e0 = fast_exp(v0 - mm), e1 = fast_exp(v1 - mm), e2 = fast_exp(v2 - mm);
    float s = e0 + e1 + e2;
    #pragma unroll
    for (int o = 16; o; o >>= 1) s += __shfl_xor_sync(0xffffffffu, s, o);
    __syncthreads();
    if ((tid & 31) == 0) sred[tid >> 5] = s;
    __syncthreads();
    float ss = 0.f;
    #pragma unroll
    for (int i = 0; i < 8; i++) ss += sred[i];
    float rc = 1.f / ss;
    row[tid] = e0*rc; row[tid+256] = e1*rc; row[tid+512] = e2*rc;
}

// =====================================================================
// K4: r2d = attn @ act_2d. 768 blocks x 512 threads (4-way j split).
// Weight loads vectorized to 3x LDS.128 (broadcast within warp).
// =====================================================================
__global__ void k4_r2d(const float* __restrict__ act2d) {
    int q = blockIdx.x;
    int tid = threadIdx.x; // 512
    __shared__ float s_at[NN*12]; // [j][h] transposed, rows 48B
    for (int i = tid; i < NN*HH; i += 512) {
        int h = i / NN, j = i % NN;
        s_at[j*12 + h] = g_attn[(size_t)q*(HH*NN) + i];
    }
    __syncthreads();
    int c = tid & 127, part = tid >> 7;
    ull acc2[6];
    ull z = pack2(0.f, 0.f);
    #pragma unroll
    for (int hh = 0; hh < 6; hh++) acc2[hh] = z;

    const float* base = act2d + ((size_t)q*NN + part*192)*C2d + c;
    #pragma unroll 4
    for (int j = 0; j < 192; j++) {
        float a = __ldg(base + (size_t)j*C2d);
        const ull* w = (const ull*)(s_at + (part*192 + j)*12);
        ulonglong2 w01 = *(const ulonglong2*)(w);
        ulonglong2 w23 = *(const ulonglong2*)(w+2);
        ulonglong2 w45 = *(const ulonglong2*)(w+4);
        ull a2 = pack2(a, a);
        acc2[0] = ffma2(a2, w01.x, acc2[0]);
        acc2[1] = ffma2(a2, w01.y, acc2[1]);
        acc2[2] = ffma2(a2, w23.x, acc2[2]);
        acc2[3] = ffma2(a2, w23.y, acc2[3]);
        acc2[4] = ffma2(a2, w45.x, acc2[4]);
        acc2[5] = ffma2(a2, w45.y, acc2[5]);
    }
    __syncthreads();
    #pragma unroll
    for (int hh = 0; hh < 6; hh++) {
        float2 v = unpack2(acc2[hh]);
        s_at[(part*128 + c)*12 + 2*hh]   = v.x;
        s_at[(part*128 + c)*12 + 2*hh+1] = v.y;
    }
    __syncthreads();
    for (int i = tid; i < 128*12; i += 512) {
        int cc = i / 12, hh = i % 12;
        float s = 0.f;
        #pragma unroll
        for (int p = 0; p < 4; p++) s += s_at[(p*128 + cc)*12 + hh];
        g_cbuf[q*CONCAT + 576 + hh*128 + cc] = s;
    }
}

// =====================================================================
// K5: attn @ [v | vp] per head, register-tiled (2q x 5c per thread).
// =====================================================================
__global__ void k5_av() {
    __shared__ float sA[64][65];
    __shared__ float sB[64][40];
    int h = blockIdx.y;
    int q0 = blockIdx.x * 64;
    int tid = threadIdx.x;
    int tc = tid & 7, tr = tid >> 3;
    float acc[2][5];
    #pragma unroll
    for (int i = 0; i < 2; i++)
        #pragma unroll
        for (int j = 0; j < 5; j++) acc[i][j] = 0.f;

    for (int k0 = 0; k0 < NN; k0 += 64) {
        for (int i = tid; i < 64*16; i += 256) {
            int r = i >> 4, c4 = i & 15;
            float4 v = *(const float4*)(g_attn + (size_t)(q0+r)*(HH*NN) + h*NN + k0 + c4*4);
            sA[r][c4*4+0] = v.x; sA[r][c4*4+1] = v.y; sA[r][c4*4+2] = v.z; sA[r][c4*4+3] = v.w;
        }
        for (int i = tid; i < 64*40; i += 256) {
            int kk = i / 40, c = i % 40;
            sB[kk][c] = (c < 16)
                ? g_vh [h*(NN*SVd)   + (k0+kk)*SVd   + c]
                : g_vph[h*(NN*PVd*3) + (k0+kk)*PVd*3 + (c-16)];
        }
        __syncthreads();
        #pragma unroll 8
        for (int kk = 0; kk < 64; kk++) {
            float a0 = sA[tr*2][kk], a1 = sA[tr*2+1][kk];
            float b[5];
            #pragma unroll
            for (int j = 0; j < 5; j++) b[j] = sB[kk][tc*5+j];
            #pragma unroll
            for (int j = 0; j < 5; j++) { acc[0][j] += a0*b[j]; acc[1][j] += a1*b[j]; }
        }
        __syncthreads();
    }
    #pragma unroll
    for (int i = 0; i < 2; i++) {
        int q = q0 + tr*2 + i;
        #pragma unroll
        for (int j = 0; j < 5; j++) {
            int c = tc*5 + j;
            if (c < 16) g_cbuf[q*CONCAT + h*16 + c] = acc[i][j];
            else        g_rpg [q*(HH*PVd*3) + h*(PVd*3) + (c-16)] = acc[i][j];
        }
    }
}

// =====================================================================
// K5b: invert frames + norms.
// =====================================================================
__global__ void k5b_fin(const float* __restrict__ rot,
                        const float* __restrict__ trans) {
    int q = blockIdx.x;
    int tid = threadIdx.x; // 96
    float t0 = g_rpg[q*288 + tid*3+0] - trans[q*3+0];
    float t1 = g_rpg[q*288 + tid*3+1] - trans[q*3+1];
    float t2 = g_rpg[q*288 + tid*3+2] - trans[q*3+2];
    const float* R = rot + q*9;
    float r0 = R[0]*t0 + R[3]*t1 + R[6]*t2;
    float r1 = R[1]*t0 + R[4]*t1 + R[7]*t2;
    float r2 = R[2]*t0 + R[5]*t1 + R[8]*t2;
    float* cb = g_cbuf + q*CONCAT;
    cb[192 + 0*96 + tid] = r0;
    cb[192 + 1*96 + tid] = r1;
    cb[192 + 2*96 + tid] = r2;
    cb[480 + tid] = sqrtf(r0*r0 + r1*r1 + r2*r2);
}

// =====================================================================
extern "C" void kernel_launch(void* const* d_in, const int* in_sizes, int n_in,
                              void* d_out, int out_size) {
    const float* act   = (const float*)d_in[0];
    const float* act2d = (const float*)d_in[1];
    const float* smask = (const float*)d_in[2];
    const float* rot   = (const float*)d_in[3];
    const float* trans = (const float*)d_in[4];
    const float* wq    = (const float*)d_in[5];
    const float* wk    = (const float*)d_in[6];
    const float* wv    = (const float*)d_in[7];
    const float* wqp   = (const float*)d_in[8];
    const float* bqp   = (const float*)d_in[9];
    const float* wkp   = (const float*)d_in[10];
    const float* bkp   = (const float*)d_in[11];
    const float* wvp   = (const float*)d_in[12];
    const float* bvp   = (const float*)d_in[13];
    const float* w2d   = (const float*)d_in[14];
    const float* b2d   = (const float*)d_in[15];
    const float* wfin  = (const float*)d_in[16];
    const float* bfin  = (const float*)d_in[17];
    const float* tw    = (const float*)d_in[18];
    float* out = (float*)d_out;

    float *p_wcat, *p_bcat, *p_proj, *p_cbuf;
    cudaGetSymbolAddress((void**)&p_wcat, g_wcat);
    cudaGetSymbolAddress((void**)&p_bcat, g_bcat);
    cudaGetSymbolAddress((void**)&p_proj, g_proj);
    cudaGetSymbolAddress((void**)&p_cbuf, g_cbuf);

    kpack<<<(C1d*NPROJ + 255)/256, 256>>>(wq, wk, wv, wqp, bqp, wkp, bkp, wvp, bvp);
    gemm128<<<dim3(NN/32, NPROJ/64), 128>>>(act, p_wcat, p_bcat, p_proj, C1d, NPROJ);
    k1b<<<NN, 576>>>(rot, trans);
    k2a<<<NN*3, 128>>>(act2d, w2d, b2d);
    k2b<<<dim3(4, 12, 12), 256>>>(smask, tw);
    k3_softmax<<<NN*HH, 256>>>();
    k4_r2d<<<NN, 512>>>(act2d);
    k5_av<<<dim3(12, 12), 256>>>();
    k5b_fin<<<NN, 96>>>(rot, trans);
    gemm128<<<dim3(NN/32, 384/64), 128>>>(p_cbuf, wfin, bfin, out, CONCAT, 384);
}

// round 13
// speedup vs baseline: 1.4083x; 1.4083x over previous
#include <cuda_runtime.h>
#include <math.h>

#define NN 768
#define HH 12
#define SQKd 16
#define SVd 16
#define PQKd 4
#define PVd 8
#define C1d 384
#define C2d 128
#define CONCAT 2112   // H*(SV + 4*PV + C2) = 12*176
#define NPROJ 1152    // 192*3 + 144*2 + 288

// -------- scratch (device globals; no allocation allowed) --------
__device__ __align__(16) float g_wcat[C1d*NPROJ];
__device__ __align__(16) float g_bcat[NPROJ];
__device__ __align__(16) float g_proj[NN*NPROJ];
__device__ __align__(16) float g_q  [NN*HH*SQKd];
__device__ __align__(16) float g_k  [NN*HH*SQKd];
__device__ __align__(16) float g_vh [HH*NN*SVd];
__device__ __align__(16) float g_qp [NN*HH*PQKd*3];
__device__ __align__(16) float g_kp [NN*HH*PQKd*3];
__device__ __align__(16) float g_vph[HH*NN*PVd*3];
__device__ __align__(16) float g_sq [NN*HH];
__device__ __align__(16) float g_sk [NN*HH];
__device__ __align__(16) float g_attn[(size_t)NN*HH*NN]; // [q][h][k]
__device__ __align__(16) float g_rpg[NN*HH*PVd*3];
__device__ __align__(16) float g_cbuf[NN*CONCAT];

// -------- f32x2 packed math helpers --------
typedef unsigned long long ull;
__device__ __forceinline__ ull pack2(float x, float y) {
    ull r; asm("mov.b64 %0, {%1, %2};" : "=l"(r) : "f"(x), "f"(y)); return r;
}
__device__ __forceinline__ float2 unpack2(ull v) {
    float2 r; asm("mov.b64 {%0, %1}, %2;" : "=f"(r.x), "=f"(r.y) : "l"(v)); return r;
}
__device__ __forceinline__ ull ffma2(ull a, ull b, ull c) {
    ull d; asm("fma.rn.f32x2 %0, %1, %2, %3;" : "=l"(d) : "l"(a), "l"(b), "l"(c)); return d;
}
__device__ __forceinline__ ull add2(ull a, ull b) {
    ull d; asm("add.rn.f32x2 %0, %1, %2;" : "=l"(d) : "l"(a), "l"(b)); return d;
}

// fast exp: 2^(x*log2e), range-reduced, degree-4 poly on FMA pipe.
__device__ __forceinline__ float fast_exp(float x) {
    float y = x * 1.44269504089f;
    y = fmaxf(y, -126.0f);
    float i = rintf(y);
    float f = y - i;
    float p = 0.00961804886f;
    p = fmaf(p, f, 0.05550410866f);
    p = fmaf(p, f, 0.24022650696f);
    p = fmaf(p, f, 0.69314718056f);
    p = fmaf(p, f, 1.0f);
    float s = __int_as_float(((int)i + 127) << 23);
    return p * s;
}

// =====================================================================
// KP: pack projection weights into one concat matrix [384 x 1152] + bias
// =====================================================================
__global__ void kpack(const float* __restrict__ wq, const float* __restrict__ wk,
                      const float* __restrict__ wv,
                      const float* __restrict__ wqp, const float* __restrict__ bqp,
                      const float* __restrict__ wkp, const float* __restrict__ bkp,
                      const float* __restrict__ wvp, const float* __restrict__ bvp) {
    int idx = blockIdx.x*256 + threadIdx.x;
    if (idx >= C1d*NPROJ) return;
    int c = idx / NPROJ, col = idx % NPROJ;
    float v;
    if (col < 192)      v = wq [c*192 + col];
    else if (col < 384) v = wk [c*192 + col-192];
    else if (col < 576) v = wv [c*192 + col-384];
    else if (col < 720) v = wqp[c*144 + col-576];
    else if (col < 864) v = wkp[c*144 + col-720];
    else                v = wvp[c*288 + col-864];
    g_wcat[idx] = v;
    if (c == 0) {
        float b = 0.f;
        if (col >= 576 && col < 720) b = bqp[col-576];
        else if (col >= 720 && col < 864) b = bkp[col-720];
        else if (col >= 864) b = bvp[col-864];
        g_bcat[col] = b;
    }
}

// =====================================================================
// gemm32: C[M,N] = A[M,K] @ B[K,N] + bias[N]. Tile 32m x 64n, kc=16.
// =====================================================================
__global__ void gemm32(const float* __restrict__ A, const float* __restrict__ B,
                       const float* __restrict__ bias, float* __restrict__ C,
                       int K, int N) {
    __shared__ float sAT[16][34];
    __shared__ float sB[16][68];
    int m0 = blockIdx.x * 32, n0 = blockIdx.y * 64;
    int tid = threadIdx.x;
    int tx = tid & 15, ty = tid >> 4;
    ull acc2[2][2];
    ull z = pack2(0.f, 0.f);
    acc2[0][0]=z; acc2[0][1]=z; acc2[1][0]=z; acc2[1][1]=z;

    for (int k0 = 0; k0 < K; k0 += 16) {
        if (tid < 128) {
            int row = tid >> 2, cp = (tid & 3) * 4;
            float4 a = *(const float4*)(A + (size_t)(m0+row)*K + k0 + cp);
            sAT[cp+0][row]=a.x; sAT[cp+1][row]=a.y; sAT[cp+2][row]=a.z; sAT[cp+3][row]=a.w;
        }
        {
            int r = tid >> 4, c = (tid & 15) * 4;
            float4 b = *(const float4*)(B + (size_t)(k0+r)*N + n0 + c);
            sB[r][c]=b.x; sB[r][c+1]=b.y; sB[r][c+2]=b.z; sB[r][c+3]=b.w;
        }
        __syncthreads();
        #pragma unroll
        for (int kk = 0; kk < 16; kk++) {
            float2 a = *(const float2*)&sAT[kk][ty*2];
            ull b20 = *(const ull*)&sB[kk][tx*4];
            ull b21 = *(const ull*)&sB[kk][tx*4+2];
            ull a20 = pack2(a.x, a.x), a21 = pack2(a.y, a.y);
            acc2[0][0] = ffma2(a20, b20, acc2[0][0]);
            acc2[0][1] = ffma2(a20, b21, acc2[0][1]);
            acc2[1][0] = ffma2(a21, b20, acc2[1][0]);
            acc2[1][1] = ffma2(a21, b21, acc2[1][1]);
        }
        __syncthreads();
    }
    #pragma unroll
    for (int i = 0; i < 2; i++) {
        float2 v0 = unpack2(acc2[i][0]);
        float2 v1 = unpack2(acc2[i][1]);
        float* dst = C + (size_t)(m0+ty*2+i)*N + n0 + tx*4;
        dst[0] = v0.x + bias[n0+tx*4+0];
        dst[1] = v0.y + bias[n0+tx*4+1];
        dst[2] = v1.x + bias[n0+tx*4+2];
        dst[3] = v1.y + bias[n0+tx*4+3];
    }
}

// =====================================================================
// K1b: scatter q/k/v, apply rigid frames to points, compute sq/sk.
// =====================================================================
__global__ void k1b(const float* __restrict__ rot, const float* __restrict__ trans) {
    int n = blockIdx.x;
    int tid = threadIdx.x; // 576
    __shared__ float s_p[NPROJ];
    __shared__ float s_app[96*3];
    __shared__ float s_rot[9], s_tr[3];
    for (int i = tid; i < NPROJ; i += 576) s_p[i] = g_proj[(size_t)n*NPROJ + i];
    if (tid < 9) s_rot[tid] = rot[n*9 + tid];
    if (tid < 3) s_tr[tid]  = trans[n*3 + tid];
    __syncthreads();

    if (tid < 192)      g_q[n*192 + tid] = s_p[tid] * 0.25f;
    else if (tid < 384) { int o = tid-192; g_k[n*192 + o] = s_p[192 + o]; }
    else { int o = tid-384; g_vh[(o >> 4)*(NN*SVd) + n*SVd + (o & 15)] = s_p[384 + o]; }

    const float* raw = s_p + 576;
    if (tid < 192) {
        float l0, l1, l2;
        if (tid < 48) {
            int h = tid >> 2, p = tid & 3;
            l0 = raw[h*12 + p]; l1 = raw[h*12 + 4 + p]; l2 = raw[h*12 + 8 + p];
        } else if (tid < 96) {
            int j = tid - 48; int h = j >> 2, p = j & 3;
            l0 = raw[144 + h*12 + p]; l1 = raw[144 + h*12 + 4 + p]; l2 = raw[144 + h*12 + 8 + p];
        } else {
            int j = tid - 96; int h = j >> 3, p = j & 7;
            l0 = raw[288 + h*24 + p]; l1 = raw[288 + h*24 + 8 + p]; l2 = raw[288 + h*24 + 16 + p];
        }
        float gx = s_rot[0]*l0 + s_rot[1]*l1 + s_rot[2]*l2 + s_tr[0];
        float gy = s_rot[3]*l0 + s_rot[4]*l1 + s_rot[5]*l2 + s_tr[1];
        float gz = s_rot[6]*l0 + s_rot[7]*l1 + s_rot[8]*l2 + s_tr[2];
        if (tid < 48) {
            g_qp[n*144 + tid*3+0] = gx; g_qp[n*144 + tid*3+1] = gy; g_qp[n*144 + tid*3+2] = gz;
            s_app[tid*3+0] = gx; s_app[tid*3+1] = gy; s_app[tid*3+2] = gz;
        } else if (tid < 96) {
            int j = tid - 48;
            g_kp[n*144 + j*3+0] = gx; g_kp[n*144 + j*3+1] = gy; g_kp[n*144 + j*3+2] = gz;
            s_app[tid*3+0] = gx; s_app[tid*3+1] = gy; s_app[tid*3+2] = gz;
        } else {
            int j = tid - 96; int h = j >> 3, p = j & 7;
            g_vph[h*(NN*PVd*3) + n*(PVd*3) + p*3+0] = gx;
            g_vph[h*(NN*PVd*3) + n*(PVd*3) + p*3+1] = gy;
            g_vph[h*(NN*PVd*3) + n*(PVd*3) + p*3+2] = gz;
        }
    }
    __syncthreads();
    if (tid < 24) {
        int h = tid % 12;
        int base = (tid < 12) ? 0 : 144;
        float s = 0.f;
        #pragma unroll
        for (int p = 0; p < 4; p++) {
            float x = s_app[base + (h*4+p)*3+0];
            float y = s_app[base + (h*4+p)*3+1];
            float z = s_app[base + (h*4+p)*3+2];
            s += x*x + y*y + z*z;
        }
        if (tid < 12) g_sq[n*12 + h] = s; else g_sk[n*12 + h] = s;
    }
}

// =====================================================================
// K2a v4 (proven 86.5us): Z = act2d @ w2d + b2d -> g_attn[q][h][k].
// Grid (q, 256-k chunk) = 2304 blocks, 128 threads, 2 k per thread.
// Coalesced staging into s_a[256][33]; weights via 3x LDS.128 broadcast.
// =====================================================================
__global__ void k2a(const float* __restrict__ act2d,
                    const float* __restrict__ w2d,
                    const float* __restrict__ b2d) {
    __shared__ float s_a[256][33];
    __shared__ ull s_w[128][6];
    int tid = threadIdx.x;  // 128
    int q = blockIdx.x / 3, k0 = (blockIdx.x % 3) * 256;

    for (int i = tid; i < 768; i += 128) {
        int c = i / 6, hh = i % 6;
        s_w[c][hh] = pack2(w2d[c*12 + hh*2], w2d[c*12 + hh*2 + 1]);
    }
    ull acc[2][6];
    #pragma unroll
    for (int hh = 0; hh < 6; hh++) {
        ull b = pack2(b2d[2*hh], b2d[2*hh+1]);
        acc[0][hh] = b; acc[1][hh] = b;
    }

    const float* base = act2d + ((size_t)q*NN + k0)*C2d;
    for (int c0 = 0; c0 < 128; c0 += 32) {
        __syncthreads();
        // stage 256 rows x 32 channels: 2048 float4, coalesced (8 thr/row)
        #pragma unroll
        for (int it = 0; it < 16; it++) {
            int i = it*128 + tid;
            int r = i >> 3, c4 = i & 7;
            float4 v = *(const float4*)(base + (size_t)r*C2d + c0 + c4*4);
            s_a[r][c4*4+0] = v.x; s_a[r][c4*4+1] = v.y;
            s_a[r][c4*4+2] = v.z; s_a[r][c4*4+3] = v.w;
        }
        __syncthreads();
        #pragma unroll 8
        for (int c = 0; c < 32; c++) {
            float a0 = s_a[tid][c];
            float a1 = s_a[tid+128][c];
            const ull* wr = s_w[c0 + c];
            ulonglong2 w01 = *(const ulonglong2*)(wr);
            ulonglong2 w23 = *(const ulonglong2*)(wr+2);
            ulonglong2 w45 = *(const ulonglong2*)(wr+4);
            ull p0 = pack2(a0, a0);
            ull p1 = pack2(a1, a1);
            acc[0][0] = ffma2(p0, w01.x, acc[0][0]);
            acc[0][1] = ffma2(p0, w01.y, acc[0][1]);
            acc[0][2] = ffma2(p0, w23.x, acc[0][2]);
            acc[0][3] = ffma2(p0, w23.y, acc[0][3]);
            acc[0][4] = ffma2(p0, w45.x, acc[0][4]);
            acc[0][5] = ffma2(p0, w45.y, acc[0][5]);
            acc[1][0] = ffma2(p1, w01.x, acc[1][0]);
            acc[1][1] = ffma2(p1, w01.y, acc[1][1]);
            acc[1][2] = ffma2(p1, w23.x, acc[1][2]);
            acc[1][3] = ffma2(p1, w23.y, acc[1][3]);
            acc[1][4] = ffma2(p1, w45.x, acc[1][4]);
            acc[1][5] = ffma2(p1, w45.y, acc[1][5]);
        }
    }
    #pragma unroll
    for (int kk = 0; kk < 2; kk++) {
        float* dst = g_attn + (size_t)q*(HH*NN) + k0 + kk*128 + tid;
        #pragma unroll
        for (int hh = 0; hh < 6; hh++) {
            float2 v = unpack2(acc[kk][hh]);
            dst[(size_t)(2*hh)*NN]   = v.x;
            dst[(size_t)(2*hh+1)*NN] = v.y;
        }
    }
}

// =====================================================================
// K2b: add qk-dot + point-distance + mask terms, scale. Per head.
// =====================================================================
__global__ void k2b(const float* __restrict__ smask, const float* __restrict__ tw) {
    int k0 = blockIdx.x * 192, q0 = blockIdx.y * 64, h = blockIdx.z;
    int tid = threadIdx.x;
    __shared__ float s_qc[64][28];
    __shared__ float s_kc[28][192];
    __shared__ float s_sq[64], s_sk[192], s_mq[64], s_mk[192];
    float pw = 0.23570226039f * log1pf(expf(tw[h]));

    for (int i = tid; i < 64*16;  i += 256) { int r=i>>4, c=i&15;  s_qc[r][c]    = g_q [(q0+r)*192 + h*16 + c]; }
    for (int i = tid; i < 64*12;  i += 256) { int r=i/12, c=i%12;  s_qc[r][16+c] = pw * g_qp[(q0+r)*144 + h*12 + c]; }
    for (int i = tid; i < 192*16; i += 256) { int kk=i>>4, c=i&15; s_kc[c][kk]    = g_k [(k0+kk)*192 + h*16 + c]; }
    for (int i = tid; i < 192*12; i += 256) { int kk=i/12, c=i%12; s_kc[16+c][kk] = g_kp[(k0+kk)*144 + h*12 + c]; }
    if (tid < 64)  { s_sq[tid] = g_sq[(q0+tid)*12 + h]; s_mq[tid] = smask[q0+tid]; }
    if (tid < 192) { s_sk[tid] = g_sk[(k0+tid)*12 + h]; s_mk[tid] = smask[k0+tid]; }
    __syncthreads();

    int tc = tid & 31, tr = tid >> 5;
    ull acc2[8][3];
    ull z = pack2(0.f, 0.f);
    #pragma unroll
    for (int i = 0; i < 8; i++) { acc2[i][0]=z; acc2[i][1]=z; acc2[i][2]=z; }

    #pragma unroll 4
    for (int c = 0; c < 28; c++) {
        const float* kr = &s_kc[c][tc];
        ull b2[3];
        #pragma unroll
        for (int jp = 0; jp < 3; jp++) b2[jp] = pack2(kr[32*(2*jp)], kr[32*(2*jp+1)]);
        #pragma unroll
        for (int i = 0; i < 8; i++) {
            float a = s_qc[tr*8+i][c];
            ull a2 = pack2(a, a);
            acc2[i][0] = ffma2(a2, b2[0], acc2[i][0]);
            acc2[i][1] = ffma2(a2, b2[1], acc2[i][1]);
            acc2[i][2] = ffma2(a2, b2[2], acc2[i][2]);
        }
    }
    #pragma unroll
    for (int i = 0; i < 8; i++) {
        int q = q0 + tr*8 + i;
        float sqv = s_sq[tr*8+i], mq = s_mq[tr*8+i];
        float* row = g_attn + (size_t)q*(HH*NN) + h*NN + k0 + tc;
        #pragma unroll
        for (int jp = 0; jp < 3; jp++) {
            float2 v = unpack2(acc2[i][jp]);
            int j0 = 32*(2*jp), j1 = 32*(2*jp+1);
            float l0 = row[j0] + v.x - 0.5f*pw*(sqv + s_sk[tc+j0]) - 1e5f*(1.f - mq*s_mk[tc+j0]);
            float l1 = row[j1] + v.y - 0.5f*pw*(sqv + s_sk[tc+j1]) - 1e5f*(1.f - mq*s_mk[tc+j1]);
            row[j0] = l0 * 0.57735026919f;
            row[j1] = l1 * 0.57735026919f;
        }
    }
}

// =====================================================================
// K3: softmax over keys. 9216 rows of 768, poly exp on FMA pipe.
// =====================================================================
__global__ void k3_softmax() {
    int r = blockIdx.x;
    float* row = g_attn + (size_t)r*NN;
    int tid = threadIdx.x;
    float v0 = row[tid], v1 = row[tid+256], v2 = row[tid+512];
    float m = fmaxf(fmaxf(v0, v1), v2);
    __shared__ float sred[8];
    #pragma unroll
    for (int o = 16; o; o >>= 1) m = fmaxf(m, __shfl_xor_sync(0xffffffffu, m, o));
    if ((tid & 31) == 0) sred[tid >> 5] = m;
    __syncthreads();
    float mm = sred[0];
    #pragma unroll
    for (int i = 1; i < 8; i++) mm = fmaxf(mm, sred[i]);
    float e0 = fast_exp(v0 - mm), e1 = fast_exp(v1 - mm), e2 = fast_exp(v2 - mm);
    float s = e0 + e1 + e2;
    #pragma unroll
    for (int o = 16; o; o >>= 1) s += __shfl_xor_sync(0xffffffffu, s, o);
    __syncthreads();
    if ((tid & 31) == 0) sred[tid >> 5] = s;
    __syncthreads();
    float ss = 0.f;
    #pragma unroll
    for (int i = 0; i < 8; i++) ss += sred[i];
    float rc = 1.f / ss;
    row[tid] = e0*rc; row[tid+256] = e1*rc; row[tid+512] = e2*rc;
}

// =====================================================================
// K4 v3: r2d = attn @ act_2d. 768 blocks x 256 threads.
// Thread = (part p of 8, channel-group g of 32). p owns 96 j-rows,
// g owns 4 channels (one float4 LDG, warp covers 512B contiguous).
// Per j: 1 LDG.128 + 3 LDS.128 broadcast -> 24 FFMA2 (was 4 LSU : 6).
// Final 8-part reduction via smem buffer overlaid on s_at (4 rounds).
// =====================================================================
__global__ void __launch_bounds__(256) k4_r2d(const float* __restrict__ act2d) {
    int q = blockIdx.x;
    int tid = threadIdx.x; // 256
    __shared__ __align__(16) float s_at[NN*12]; // [j][h], 36.9KB
    for (int i = tid; i < NN*HH; i += 256) {
        int h = i / NN, j = i % NN;
        s_at[j*12 + h] = g_attn[(size_t)q*(HH*NN) + i];
    }
    __syncthreads();

    int g = tid & 31;   // channel group -> channels g*4 .. g*4+3
    int p = tid >> 5;   // part 0..7 -> rows p*96 .. p*96+95
    ull acc[4][6];
    ull z = pack2(0.f, 0.f);
    #pragma unroll
    for (int c = 0; c < 4; c++)
        #pragma unroll
        for (int hh = 0; hh < 6; hh++) acc[c][hh] = z;

    const float* base = act2d + ((size_t)q*NN + p*96)*C2d + g*4;
    #pragma unroll 4
    for (int j = 0; j < 96; j++) {
        float4 a = *(const float4*)(base + (size_t)j*C2d);
        const ull* w = (const ull*)(s_at + (p*96 + j)*12);
        ulonglong2 w01 = *(const ulonglong2*)(w);
        ulonglong2 w23 = *(const ulonglong2*)(w+2);
        ulonglong2 w45 = *(const ulonglong2*)(w+4);
        float av[4] = {a.x, a.y, a.z, a.w};
        #pragma unroll
        for (int c = 0; c < 4; c++) {
            ull a2 = pack2(av[c], av[c]);
            acc[c][0] = ffma2(a2, w01.x, acc[c][0]);
            acc[c][1] = ffma2(a2, w01.y, acc[c][1]);
            acc[c][2] = ffma2(a2, w23.x, acc[c][2]);
            acc[c][3] = ffma2(a2, w23.y, acc[c][3]);
            acc[c][4] = ffma2(a2, w45.x, acc[c][4]);
            acc[c][5] = ffma2(a2, w45.y, acc[c][5]);
        }
    }

    // reduce across the 8 parts, one channel-within-group per round
    ull* rb = (ull*)s_at;   // [8][32][6] = 1536 ull = 12.3KB, fits in s_at
    float* cb = g_cbuf + (size_t)q*CONCAT + 576;
    #pragma unroll
    for (int c = 0; c < 4; c++) {
        __syncthreads();   // round 0: also guards s_at attn reads above
        #pragma unroll
        for (int hh = 0; hh < 6; hh++) rb[p*192 + g*6 + hh] = acc[c][hh];
        __syncthreads();
        if (tid < 192) {
            ull s = rb[tid];
            #pragma unroll
            for (int p2 = 1; p2 < 8; p2++) s = add2(s, rb[p2*192 + tid]);
            int g2 = tid / 6, hh = tid % 6;
            float2 v = unpack2(s);
            int ch = g2*4 + c;
            cb[(2*hh)*128 + ch]   = v.x;
            cb[(2*hh+1)*128 + ch] = v.y;
        }
    }
}

// =====================================================================
// K5: attn @ [v | vp] per head, register-tiled (2q x 5c per thread).
// =====================================================================
__global__ void k5_av() {
    __shared__ float sA[64][65];
    __shared__ float sB[64][40];
    int h = blockIdx.y;
    int q0 = blockIdx.x * 64;
    int tid = threadIdx.x;
    int tc = tid & 7, tr = tid >> 3;
    float acc[2][5];
    #pragma unroll
    for (int i = 0; i < 2; i++)
        #pragma unroll
        for (int j = 0; j < 5; j++) acc[i][j] = 0.f;

    for (int k0 = 0; k0 < NN; k0 += 64) {
        for (int i = tid; i < 64*16; i += 256) {
            int r = i >> 4, c4 = i & 15;
            float4 v = *(const float4*)(g_attn + (size_t)(q0+r)*(HH*NN) + h*NN + k0 + c4*4);
            sA[r][c4*4+0] = v.x; sA[r][c4*4+1] = v.y; sA[r][c4*4+2] = v.z; sA[r][c4*4+3] = v.w;
        }
        for (int i = tid; i < 64*40; i += 256) {
            int kk = i / 40, c = i % 40;
            sB[kk][c] = (c < 16)
                ? g_vh [h*(NN*SVd)   + (k0+kk)*SVd   + c]
                : g_vph[h*(NN*PVd*3) + (k0+kk)*PVd*3 + (c-16)];
        }
        __syncthreads();
        #pragma unroll 8
        for (int kk = 0; kk < 64; kk++) {
            float a0 = sA[tr*2][kk], a1 = sA[tr*2+1][kk];
            float b[5];
            #pragma unroll
            for (int j = 0; j < 5; j++) b[j] = sB[kk][tc*5+j];
            #pragma unroll
            for (int j = 0; j < 5; j++) { acc[0][j] += a0*b[j]; acc[1][j] += a1*b[j]; }
        }
        __syncthreads();
    }
    #pragma unroll
    for (int i = 0; i < 2; i++) {
        int q = q0 + tr*2 + i;
        #pragma unroll
        for (int j = 0; j < 5; j++) {
            int c = tc*5 + j;
            if (c < 16) g_cbuf[q*CONCAT + h*16 + c] = acc[i][j];
            else        g_rpg [q*(HH*PVd*3) + h*(PVd*3) + (c-16)] = acc[i][j];
        }
    }
}

// =====================================================================
// K5b: invert frames + norms.
// =====================================================================
__global__ void k5b_fin(const float* __restrict__ rot,
                        const float* __restrict__ trans) {
    int q = blockIdx.x;
    int tid = threadIdx.x; // 96
    float t0 = g_rpg[q*288 + tid*3+0] - trans[q*3+0];
    float t1 = g_rpg[q*288 + tid*3+1] - trans[q*3+1];
    float t2 = g_rpg[q*288 + tid*3+2] - trans[q*3+2];
    const float* R = rot + q*9;
    float r0 = R[0]*t0 + R[3]*t1 + R[6]*t2;
    float r1 = R[1]*t0 + R[4]*t1 + R[7]*t2;
    float r2 = R[2]*t0 + R[5]*t1 + R[8]*t2;
    float* cb = g_cbuf + q*CONCAT;
    cb[192 + 0*96 + tid] = r0;
    cb[192 + 1*96 + tid] = r1;
    cb[192 + 2*96 + tid] = r2;
    cb[480 + tid] = sqrtf(r0*r0 + r1*r1 + r2*r2);
}

// =====================================================================
extern "C" void kernel_launch(void* const* d_in, const int* in_sizes, int n_in,
                              void* d_out, int out_size) {
    const float* act   = (const float*)d_in[0];
    const float* act2d = (const float*)d_in[1];
    const float* smask = (const float*)d_in[2];
    const float* rot   = (const float*)d_in[3];
    const float* trans = (const float*)d_in[4];
    const float* wq    = (const float*)d_in[5];
    const float* wk    = (const float*)d_in[6];
    const float* wv    = (const float*)d_in[7];
    const float* wqp   = (const float*)d_in[8];
    const float* bqp   = (const float*)d_in[9];
    const float* wkp   = (const float*)d_in[10];
    const float* bkp   = (const float*)d_in[11];
    const float* wvp   = (const float*)d_in[12];
    const float* bvp   = (const float*)d_in[13];
    const float* w2d   = (const float*)d_in[14];
    const float* b2d   = (const float*)d_in[15];
    const float* wfin  = (const float*)d_in[16];
    const float* bfin  = (const float*)d_in[17];
    const float* tw    = (const float*)d_in[18];
    float* out = (float*)d_out;

    float *p_wcat, *p_bcat, *p_proj, *p_cbuf;
    cudaGetSymbolAddress((void**)&p_wcat, g_wcat);
    cudaGetSymbolAddress((void**)&p_bcat, g_bcat);
    cudaGetSymbolAddress((void**)&p_proj, g_proj);
    cudaGetSymbolAddress((void**)&p_cbuf, g_cbuf);

    kpack<<<(C1d*NPROJ + 255)/256, 256>>>(wq, wk, wv, wqp, bqp, wkp, bkp, wvp, bvp);
    gemm32<<<dim3(NN/32, NPROJ/64), 256>>>(act, p_wcat, p_bcat, p_proj, C1d, NPROJ);
    k1b<<<NN, 576>>>(rot, trans);
    k2a<<<NN*3, 128>>>(act2d, w2d, b2d);
    k2b<<<dim3(4, 12, 12), 256>>>(smask, tw);
    k3_softmax<<<NN*HH, 256>>>();
    k4_r2d<<<NN, 256>>>(act2d);
    k5_av<<<dim3(12, 12), 256>>>();
    k5b_fin<<<NN, 96>>>(rot, trans);
    gemm32<<<dim3(NN/32, 384/64), 256>>>(p_cbuf, wfin, bfin, out, CONCAT, 384);
}

// round 14
// speedup vs baseline: 1.5078x; 1.0707x over previous
#include <cuda_runtime.h>
#include <math.h>

#define NN 768
#define HH 12
#define SQKd 16
#define SVd 16
#define PQKd 4
#define PVd 8
#define C1d 384
#define C2d 128
#define CONCAT 2112   // H*(SV + 4*PV + C2) = 12*176
#define NPROJ 1152    // 192*3 + 144*2 + 288

// -------- scratch (device globals; no allocation allowed) --------
__device__ __align__(16) float g_wcat[C1d*NPROJ];
__device__ __align__(16) float g_bcat[NPROJ];
__device__ __align__(16) float g_proj[NN*NPROJ];
__device__ __align__(16) float g_q  [NN*HH*SQKd];
__device__ __align__(16) float g_k  [NN*HH*SQKd];
__device__ __align__(16) float g_vh [HH*NN*SVd];
__device__ __align__(16) float g_qp [NN*HH*PQKd*3];
__device__ __align__(16) float g_kp [NN*HH*PQKd*3];
__device__ __align__(16) float g_vph[HH*NN*PVd*3];
__device__ __align__(16) float g_sq [NN*HH];
__device__ __align__(16) float g_sk [NN*HH];
__device__ __align__(16) float g_attn[(size_t)NN*HH*NN]; // [q][h][k]
__device__ __align__(16) float g_rpg[NN*HH*PVd*3];
__device__ __align__(16) float g_cbuf[NN*CONCAT];

// -------- f32x2 packed math helpers --------
typedef unsigned long long ull;
__device__ __forceinline__ ull pack2(float x, float y) {
    ull r; asm("mov.b64 %0, {%1, %2};" : "=l"(r) : "f"(x), "f"(y)); return r;
}
__device__ __forceinline__ float2 unpack2(ull v) {
    float2 r; asm("mov.b64 {%0, %1}, %2;" : "=f"(r.x), "=f"(r.y) : "l"(v)); return r;
}
__device__ __forceinline__ ull ffma2(ull a, ull b, ull c) {
    ull d; asm("fma.rn.f32x2 %0, %1, %2, %3;" : "=l"(d) : "l"(a), "l"(b), "l"(c)); return d;
}
__device__ __forceinline__ ull add2(ull a, ull b) {
    ull d; asm("add.rn.f32x2 %0, %1, %2;" : "=l"(d) : "l"(a), "l"(b)); return d;
}

// -------- cp.async helpers --------
__device__ __forceinline__ unsigned smem_u32(const void* p) {
    unsigned s;
    asm("{ .reg .u64 t; cvta.to.shared.u64 t, %1; cvt.u32.u64 %0, t; }"
        : "=r"(s) : "l"(p));
    return s;
}
__device__ __forceinline__ void cp_async16(void* dst_smem, const void* src_gmem) {
    asm volatile("cp.async.cg.shared.global [%0], [%1], 16;"
                 :: "r"(smem_u32(dst_smem)), "l"(src_gmem) : "memory");
}
__device__ __forceinline__ void cp_commit() {
    asm volatile("cp.async.commit_group;" ::: "memory");
}
template<int N>
__device__ __forceinline__ void cp_wait() {
    asm volatile("cp.async.wait_group %0;" :: "n"(N) : "memory");
}

// fast exp: 2^(x*log2e), range-reduced, degree-4 poly on FMA pipe.
__device__ __forceinline__ float fast_exp(float x) {
    float y = x * 1.44269504089f;
    y = fmaxf(y, -126.0f);
    float i = rintf(y);
    float f = y - i;
    float p = 0.00961804886f;
    p = fmaf(p, f, 0.05550410866f);
    p = fmaf(p, f, 0.24022650696f);
    p = fmaf(p, f, 0.69314718056f);
    p = fmaf(p, f, 1.0f);
    float s = __int_as_float(((int)i + 127) << 23);
    return p * s;
}

// =====================================================================
// KP: pack projection weights into one concat matrix [384 x 1152] + bias
// =====================================================================
__global__ void kpack(const float* __restrict__ wq, const float* __restrict__ wk,
                      const float* __restrict__ wv,
                      const float* __restrict__ wqp, const float* __restrict__ bqp,
                      const float* __restrict__ wkp, const float* __restrict__ bkp,
                      const float* __restrict__ wvp, const float* __restrict__ bvp) {
    int idx = blockIdx.x*256 + threadIdx.x;
    if (idx >= C1d*NPROJ) return;
    int c = idx / NPROJ, col = idx % NPROJ;
    float v;
    if (col < 192)      v = wq [c*192 + col];
    else if (col < 384) v = wk [c*192 + col-192];
    else if (col < 576) v = wv [c*192 + col-384];
    else if (col < 720) v = wqp[c*144 + col-576];
    else if (col < 864) v = wkp[c*144 + col-720];
    else                v = wvp[c*288 + col-864];
    g_wcat[idx] = v;
    if (c == 0) {
        float b = 0.f;
        if (col >= 576 && col < 720) b = bqp[col-576];
        else if (col >= 720 && col < 864) b = bkp[col-720];
        else if (col >= 864) b = bvp[col-864];
        g_bcat[col] = b;
    }
}

// =====================================================================
// gemm32: C[M,N] = A[M,K] @ B[K,N] + bias[N]. Tile 32m x 64n, kc=16.
// =====================================================================
__global__ void gemm32(const float* __restrict__ A, const float* __restrict__ B,
                       const float* __restrict__ bias, float* __restrict__ C,
                       int K, int N) {
    __shared__ float sAT[16][34];
    __shared__ float sB[16][68];
    int m0 = blockIdx.x * 32, n0 = blockIdx.y * 64;
    int tid = threadIdx.x;
    int tx = tid & 15, ty = tid >> 4;
    ull acc2[2][2];
    ull z = pack2(0.f, 0.f);
    acc2[0][0]=z; acc2[0][1]=z; acc2[1][0]=z; acc2[1][1]=z;

    for (int k0 = 0; k0 < K; k0 += 16) {
        if (tid < 128) {
            int row = tid >> 2, cp = (tid & 3) * 4;
            float4 a = *(const float4*)(A + (size_t)(m0+row)*K + k0 + cp);
            sAT[cp+0][row]=a.x; sAT[cp+1][row]=a.y; sAT[cp+2][row]=a.z; sAT[cp+3][row]=a.w;
        }
        {
            int r = tid >> 4, c = (tid & 15) * 4;
            float4 b = *(const float4*)(B + (size_t)(k0+r)*N + n0 + c);
            sB[r][c]=b.x; sB[r][c+1]=b.y; sB[r][c+2]=b.z; sB[r][c+3]=b.w;
        }
        __syncthreads();
        #pragma unroll
        for (int kk = 0; kk < 16; kk++) {
            float2 a = *(const float2*)&sAT[kk][ty*2];
            ull b20 = *(const ull*)&sB[kk][tx*4];
            ull b21 = *(const ull*)&sB[kk][tx*4+2];
            ull a20 = pack2(a.x, a.x), a21 = pack2(a.y, a.y);
            acc2[0][0] = ffma2(a20, b20, acc2[0][0]);
            acc2[0][1] = ffma2(a20, b21, acc2[0][1]);
            acc2[1][0] = ffma2(a21, b20, acc2[1][0]);
            acc2[1][1] = ffma2(a21, b21, acc2[1][1]);
        }
        __syncthreads();
    }
    #pragma unroll
    for (int i = 0; i < 2; i++) {
        float2 v0 = unpack2(acc2[i][0]);
        float2 v1 = unpack2(acc2[i][1]);
        float* dst = C + (size_t)(m0+ty*2+i)*N + n0 + tx*4;
        dst[0] = v0.x + bias[n0+tx*4+0];
        dst[1] = v0.y + bias[n0+tx*4+1];
        dst[2] = v1.x + bias[n0+tx*4+2];
        dst[3] = v1.y + bias[n0+tx*4+3];
    }
}

// =====================================================================
// K1b: scatter q/k/v, apply rigid frames to points, compute sq/sk.
// =====================================================================
__global__ void k1b(const float* __restrict__ rot, const float* __restrict__ trans) {
    int n = blockIdx.x;
    int tid = threadIdx.x; // 576
    __shared__ float s_p[NPROJ];
    __shared__ float s_app[96*3];
    __shared__ float s_rot[9], s_tr[3];
    for (int i = tid; i < NPROJ; i += 576) s_p[i] = g_proj[(size_t)n*NPROJ + i];
    if (tid < 9) s_rot[tid] = rot[n*9 + tid];
    if (tid < 3) s_tr[tid]  = trans[n*3 + tid];
    __syncthreads();

    if (tid < 192)      g_q[n*192 + tid] = s_p[tid] * 0.25f;
    else if (tid < 384) { int o = tid-192; g_k[n*192 + o] = s_p[192 + o]; }
    else { int o = tid-384; g_vh[(o >> 4)*(NN*SVd) + n*SVd + (o & 15)] = s_p[384 + o]; }

    const float* raw = s_p + 576;
    if (tid < 192) {
        float l0, l1, l2;
        if (tid < 48) {
            int h = tid >> 2, p = tid & 3;
            l0 = raw[h*12 + p]; l1 = raw[h*12 + 4 + p]; l2 = raw[h*12 + 8 + p];
        } else if (tid < 96) {
            int j = tid - 48; int h = j >> 2, p = j & 3;
            l0 = raw[144 + h*12 + p]; l1 = raw[144 + h*12 + 4 + p]; l2 = raw[144 + h*12 + 8 + p];
        } else {
            int j = tid - 96; int h = j >> 3, p = j & 7;
            l0 = raw[288 + h*24 + p]; l1 = raw[288 + h*24 + 8 + p]; l2 = raw[288 + h*24 + 16 + p];
        }
        float gx = s_rot[0]*l0 + s_rot[1]*l1 + s_rot[2]*l2 + s_tr[0];
        float gy = s_rot[3]*l0 + s_rot[4]*l1 + s_rot[5]*l2 + s_tr[1];
        float gz = s_rot[6]*l0 + s_rot[7]*l1 + s_rot[8]*l2 + s_tr[2];
        if (tid < 48) {
            g_qp[n*144 + tid*3+0] = gx; g_qp[n*144 + tid*3+1] = gy; g_qp[n*144 + tid*3+2] = gz;
            s_app[tid*3+0] = gx; s_app[tid*3+1] = gy; s_app[tid*3+2] = gz;
        } else if (tid < 96) {
            int j = tid - 48;
            g_kp[n*144 + j*3+0] = gx; g_kp[n*144 + j*3+1] = gy; g_kp[n*144 + j*3+2] = gz;
            s_app[tid*3+0] = gx; s_app[tid*3+1] = gy; s_app[tid*3+2] = gz;
        } else {
            int j = tid - 96; int h = j >> 3, p = j & 7;
            g_vph[h*(NN*PVd*3) + n*(PVd*3) + p*3+0] = gx;
            g_vph[h*(NN*PVd*3) + n*(PVd*3) + p*3+1] = gy;
            g_vph[h*(NN*PVd*3) + n*(PVd*3) + p*3+2] = gz;
        }
    }
    __syncthreads();
    if (tid < 24) {
        int h = tid % 12;
        int base = (tid < 12) ? 0 : 144;
        float s = 0.f;
        #pragma unroll
        for (int p = 0; p < 4; p++) {
            float x = s_app[base + (h*4+p)*3+0];
            float y = s_app[base + (h*4+p)*3+1];
            float z = s_app[base + (h*4+p)*3+2];
            s += x*x + y*y + z*z;
        }
        if (tid < 12) g_sq[n*12 + h] = s; else g_sk[n*12 + h] = s;
    }
}

// =====================================================================
// K2a v7: Z = act2d @ w2d + b2d -> g_attn[q][h][k].
// Grid (q, 256-k chunk) = 2304 blocks, 128 threads, 2 k per thread.
// cp.async double-buffered staging (chunk c+1 loads while c computes).
// Acts in XOR-swizzled float4 granules: s_a4[2][256][8], granule
// c4^(r&7) -> LDS.128 reads at the 4-phase floor, 16B-aligned rows.
// Dynamic smem 70KB -> 3 blocks/SM.
// =====================================================================
__global__ void __launch_bounds__(128) k2a(
        const float* __restrict__ act2d,
        const float* __restrict__ w2d,
        const float* __restrict__ b2d) {
    extern __shared__ char dynsm[];
    float4* s_a4 = (float4*)dynsm;                 // [2][256][8]
    ull*    s_w  = (ull*)(dynsm + 2*256*8*16);     // [128][6]
    int tid = threadIdx.x;  // 128
    int q = blockIdx.x / 3, k0 = (blockIdx.x % 3) * 256;

    for (int i = tid; i < 768; i += 128) {
        int c = i / 6, hh = i % 6;
        s_w[i] = pack2(w2d[c*12 + hh*2], w2d[c*12 + hh*2 + 1]);
    }
    ull acc[2][6];
    #pragma unroll
    for (int hh = 0; hh < 6; hh++) {
        ull b = pack2(b2d[2*hh], b2d[2*hh+1]);
        acc[0][hh] = b; acc[1][hh] = b;
    }

    const float* base = act2d + ((size_t)q*NN + k0)*C2d;

    // prologue: stage chunk 0 -> buf 0
    #pragma unroll
    for (int it = 0; it < 16; it++) {
        int i = it*128 + tid;
        int r = i >> 3, c4 = i & 7;
        cp_async16(s_a4 + (size_t)r*8 + (c4 ^ (r&7)),
                   base + (size_t)r*C2d + c4*4);
    }
    cp_commit();

    #pragma unroll
    for (int ch = 0; ch < 4; ch++) {
        int buf = ch & 1;
        if (ch < 3) {
            int c0n = (ch+1)*32;
            #pragma unroll
            for (int it = 0; it < 16; it++) {
                int i = it*128 + tid;
                int r = i >> 3, c4 = i & 7;
                cp_async16(s_a4 + ((size_t)(buf^1)*256 + r)*8 + (c4 ^ (r&7)),
                           base + (size_t)r*C2d + c0n + c4*4);
            }
            cp_commit();
            cp_wait<1>();
        } else {
            cp_wait<0>();
        }
        __syncthreads();

        int c0 = ch*32;
        #pragma unroll
        for (int g4 = 0; g4 < 8; g4++) {
            int pos = g4 ^ (tid & 7);
            float4 a0 = s_a4[((size_t)buf*256 + tid)*8 + pos];
            float4 a1 = s_a4[((size_t)buf*256 + tid + 128)*8 + pos];
            float av0[4] = {a0.x, a0.y, a0.z, a0.w};
            float av1[4] = {a1.x, a1.y, a1.z, a1.w};
            #pragma unroll
            for (int u = 0; u < 4; u++) {
                const ull* wr = s_w + (size_t)(c0 + g4*4 + u)*6;
                ulonglong2 w01 = *(const ulonglong2*)(wr);
                ulonglong2 w23 = *(const ulonglong2*)(wr+2);
                ulonglong2 w45 = *(const ulonglong2*)(wr+4);
                ull p0 = pack2(av0[u], av0[u]);
                ull p1 = pack2(av1[u], av1[u]);
                acc[0][0] = ffma2(p0, w01.x, acc[0][0]);
                acc[0][1] = ffma2(p0, w01.y, acc[0][1]);
                acc[0][2] = ffma2(p0, w23.x, acc[0][2]);
                acc[0][3] = ffma2(p0, w23.y, acc[0][3]);
                acc[0][4] = ffma2(p0, w45.x, acc[0][4]);
                acc[0][5] = ffma2(p0, w45.y, acc[0][5]);
                acc[1][0] = ffma2(p1, w01.x, acc[1][0]);
                acc[1][1] = ffma2(p1, w01.y, acc[1][1]);
                acc[1][2] = ffma2(p1, w23.x, acc[1][2]);
                acc[1][3] = ffma2(p1, w23.y, acc[1][3]);
                acc[1][4] = ffma2(p1, w45.x, acc[1][4]);
                acc[1][5] = ffma2(p1, w45.y, acc[1][5]);
            }
        }
        __syncthreads();
    }
    #pragma unroll
    for (int kk = 0; kk < 2; kk++) {
        float* dst = g_attn + (size_t)q*(HH*NN) + k0 + kk*128 + tid;
        #pragma unroll
        for (int hh = 0; hh < 6; hh++) {
            float2 v = unpack2(acc[kk][hh]);
            dst[(size_t)(2*hh)*NN]   = v.x;
            dst[(size_t)(2*hh+1)*NN] = v.y;
        }
    }
}

// =====================================================================
// K2b: add qk-dot + point-distance + mask terms, scale. Per head.
// =====================================================================
__global__ void k2b(const float* __restrict__ smask, const float* __restrict__ tw) {
    int k0 = blockIdx.x * 192, q0 = blockIdx.y * 64, h = blockIdx.z;
    int tid = threadIdx.x;
    __shared__ float s_qc[64][28];
    __shared__ float s_kc[28][192];
    __shared__ float s_sq[64], s_sk[192], s_mq[64], s_mk[192];
    float pw = 0.23570226039f * log1pf(expf(tw[h]));

    for (int i = tid; i < 64*16;  i += 256) { int r=i>>4, c=i&15;  s_qc[r][c]    = g_q [(q0+r)*192 + h*16 + c]; }
    for (int i = tid; i < 64*12;  i += 256) { int r=i/12, c=i%12;  s_qc[r][16+c] = pw * g_qp[(q0+r)*144 + h*12 + c]; }
    for (int i = tid; i < 192*16; i += 256) { int kk=i>>4, c=i&15; s_kc[c][kk]    = g_k [(k0+kk)*192 + h*16 + c]; }
    for (int i = tid; i < 192*12; i += 256) { int kk=i/12, c=i%12; s_kc[16+c][kk] = g_kp[(k0+kk)*144 + h*12 + c]; }
    if (tid < 64)  { s_sq[tid] = g_sq[(q0+tid)*12 + h]; s_mq[tid] = smask[q0+tid]; }
    if (tid < 192) { s_sk[tid] = g_sk[(k0+tid)*12 + h]; s_mk[tid] = smask[k0+tid]; }
    __syncthreads();

    int tc = tid & 31, tr = tid >> 5;
    ull acc2[8][3];
    ull z = pack2(0.f, 0.f);
    #pragma unroll
    for (int i = 0; i < 8; i++) { acc2[i][0]=z; acc2[i][1]=z; acc2[i][2]=z; }

    #pragma unroll 4
    for (int c = 0; c < 28; c++) {
        const float* kr = &s_kc[c][tc];
        ull b2[3];
        #pragma unroll
        for (int jp = 0; jp < 3; jp++) b2[jp] = pack2(kr[32*(2*jp)], kr[32*(2*jp+1)]);
        #pragma unroll
        for (int i = 0; i < 8; i++) {
            float a = s_qc[tr*8+i][c];
            ull a2 = pack2(a, a);
            acc2[i][0] = ffma2(a2, b2[0], acc2[i][0]);
            acc2[i][1] = ffma2(a2, b2[1], acc2[i][1]);
            acc2[i][2] = ffma2(a2, b2[2], acc2[i][2]);
        }
    }
    #pragma unroll
    for (int i = 0; i < 8; i++) {
        int q = q0 + tr*8 + i;
        float sqv = s_sq[tr*8+i], mq = s_mq[tr*8+i];
        float* row = g_attn + (size_t)q*(HH*NN) + h*NN + k0 + tc;
        #pragma unroll
        for (int jp = 0; jp < 3; jp++) {
            float2 v = unpack2(acc2[i][jp]);
            int j0 = 32*(2*jp), j1 = 32*(2*jp+1);
            float l0 = row[j0] + v.x - 0.5f*pw*(sqv + s_sk[tc+j0]) - 1e5f*(1.f - mq*s_mk[tc+j0]);
            float l1 = row[j1] + v.y - 0.5f*pw*(sqv + s_sk[tc+j1]) - 1e5f*(1.f - mq*s_mk[tc+j1]);
            row[j0] = l0 * 0.57735026919f;
            row[j1] = l1 * 0.57735026919f;
        }
    }
}

// =====================================================================
// K3: softmax over keys. 9216 rows of 768, poly exp on FMA pipe.
// =====================================================================
__global__ void k3_softmax() {
    int r = blockIdx.x;
    float* row = g_attn + (size_t)r*NN;
    int tid = threadIdx.x;
    float v0 = row[tid], v1 = row[tid+256], v2 = row[tid+512];
    float m = fmaxf(fmaxf(v0, v1), v2);
    __shared__ float sred[8];
    #pragma unroll
    for (int o = 16; o; o >>= 1) m = fmaxf(m, __shfl_xor_sync(0xffffffffu, m, o));
    if ((tid & 31) == 0) sred[tid >> 5] = m;
    __syncthreads();
    float mm = sred[0];
    #pragma unroll
    for (int i = 1; i < 8; i++) mm = fmaxf(mm, sred[i]);
    float e0 = fast_exp(v0 - mm), e1 = fast_exp(v1 - mm), e2 = fast_exp(v2 - mm);
    float s = e0 + e1 + e2;
    #pragma unroll
    for (int o = 16; o; o >>= 1) s += __shfl_xor_sync(0xffffffffu, s, o);
    __syncthreads();
    if ((tid & 31) == 0) sred[tid >> 5] = s;
    __syncthreads();
    float ss = 0.f;
    #pragma unroll
    for (int i = 0; i < 8; i++) ss += sred[i];
    float rc = 1.f / ss;
    row[tid] = e0*rc; row[tid+256] = e1*rc; row[tid+512] = e2*rc;
}

// =====================================================================
// K4 v3: r2d = attn @ act_2d. 768 blocks x 256 threads.
// Thread = (part p of 8, channel-group g of 32). p owns 96 j-rows,
// g owns 4 channels (one float4 LDG, warp covers 512B contiguous).
// Final 8-part reduction via smem buffer overlaid on s_at (4 rounds).
// =====================================================================
__global__ void __launch_bounds__(256) k4_r2d(const float* __restrict__ act2d) {
    int q = blockIdx.x;
    int tid = threadIdx.x; // 256
    __shared__ __align__(16) float s_at[NN*12]; // [j][h], 36.9KB
    for (int i = tid; i < NN*HH; i += 256) {
        int h = i / NN, j = i % NN;
        s_at[j*12 + h] = g_attn[(size_t)q*(HH*NN) + i];
    }
    __syncthreads();

    int g = tid & 31;
    int p = tid >> 5;
    ull acc[4][6];
    ull z = pack2(0.f, 0.f);
    #pragma unroll
    for (int c = 0; c < 4; c++)
        #pragma unroll
        for (int hh = 0; hh < 6; hh++) acc[c][hh] = z;

    const float* base = act2d + ((size_t)q*NN + p*96)*C2d + g*4;
    #pragma unroll 4
    for (int j = 0; j < 96; j++) {
        float4 a = *(const float4*)(base + (size_t)j*C2d);
        const ull* w = (const ull*)(s_at + (p*96 + j)*12);
        ulonglong2 w01 = *(const ulonglong2*)(w);
        ulonglong2 w23 = *(const ulonglong2*)(w+2);
        ulonglong2 w45 = *(const ulonglong2*)(w+4);
        float av[4] = {a.x, a.y, a.z, a.w};
        #pragma unroll
        for (int c = 0; c < 4; c++) {
            ull a2 = pack2(av[c], av[c]);
            acc[c][0] = ffma2(a2, w01.x, acc[c][0]);
            acc[c][1] = ffma2(a2, w01.y, acc[c][1]);
            acc[c][2] = ffma2(a2, w23.x, acc[c][2]);
            acc[c][3] = ffma2(a2, w23.y, acc[c][3]);
            acc[c][4] = ffma2(a2, w45.x, acc[c][4]);
            acc[c][5] = ffma2(a2, w45.y, acc[c][5]);
        }
    }

    ull* rb = (ull*)s_at;
    float* cb = g_cbuf + (size_t)q*CONCAT + 576;
    #pragma unroll
    for (int c = 0; c < 4; c++) {
        __syncthreads();
        #pragma unroll
        for (int hh = 0; hh < 6; hh++) rb[p*192 + g*6 + hh] = acc[c][hh];
        __syncthreads();
        if (tid < 192) {
            ull s = rb[tid];
            #pragma unroll
            for (int p2 = 1; p2 < 8; p2++) s = add2(s, rb[p2*192 + tid]);
            int g2 = tid / 6, hh = tid % 6;
            float2 v = unpack2(s);
            int ch = g2*4 + c;
            cb[(2*hh)*128 + ch]   = v.x;
            cb[(2*hh+1)*128 + ch] = v.y;
        }
    }
}

// =====================================================================
// K5 v2: attn @ [v | vp] per head. 32-q tiles -> 288 blocks (2/SM).
// Thread owns 1 q x 5 c.
// =====================================================================
__global__ void k5_av() {
    __shared__ float sA[32][65];
    __shared__ float sB[64][40];
    int h = blockIdx.y;
    int q0 = blockIdx.x * 32;
    int tid = threadIdx.x;   // 256
    int tc = tid & 7, tr = tid >> 3;  // tr: q row 0..31, tc: 5-col group
    float acc[5] = {0.f, 0.f, 0.f, 0.f, 0.f};

    for (int k0 = 0; k0 < NN; k0 += 64) {
        for (int i = tid; i < 512; i += 256) {
            int r = i >> 4, c4 = i & 15;
            float4 v = *(const float4*)(g_attn + (size_t)(q0+r)*(HH*NN) + h*NN + k0 + c4*4);
            sA[r][c4*4+0] = v.x; sA[r][c4*4+1] = v.y; sA[r][c4*4+2] = v.z; sA[r][c4*4+3] = v.w;
        }
        for (int i = tid; i < 64*40; i += 256) {
            int kk = i / 40, c = i % 40;
            sB[kk][c] = (c < 16)
                ? g_vh [h*(NN*SVd)   + (k0+kk)*SVd   + c]
                : g_vph[h*(NN*PVd*3) + (k0+kk)*PVd*3 + (c-16)];
        }
        __syncthreads();
        #pragma unroll 8
        for (int kk = 0; kk < 64; kk++) {
            float a = sA[tr][kk];
            float b[5];
            #pragma unroll
            for (int j = 0; j < 5; j++) b[j] = sB[kk][tc*5+j];
            #pragma unroll
            for (int j = 0; j < 5; j++) acc[j] += a*b[j];
        }
        __syncthreads();
    }
    int q = q0 + tr;
    #pragma unroll
    for (int j = 0; j < 5; j++) {
        int c = tc*5 + j;
        if (c < 16) g_cbuf[q*CONCAT + h*16 + c] = acc[j];
        else        g_rpg [q*(HH*PVd*3) + h*(PVd*3) + (c-16)] = acc[j];
    }
}

// =====================================================================
// K5b: invert frames + norms.
// =====================================================================
__global__ void k5b_fin(const float* __restrict__ rot,
                        const float* __restrict__ trans) {
    int q = blockIdx.x;
    int tid = threadIdx.x; // 96
    float t0 = g_rpg[q*288 + tid*3+0] - trans[q*3+0];
    float t1 = g_rpg[q*288 + tid*3+1] - trans[q*3+1];
    float t2 = g_rpg[q*288 + tid*3+2] - trans[q*3+2];
    const float* R = rot + q*9;
    float r0 = R[0]*t0 + R[3]*t1 + R[6]*t2;
    float r1 = R[1]*t0 + R[4]*t1 + R[7]*t2;
    float r2 = R[2]*t0 + R[5]*t1 + R[8]*t2;
    float* cb = g_cbuf + q*CONCAT;
    cb[192 + 0*96 + tid] = r0;
    cb[192 + 1*96 + tid] = r1;
    cb[192 + 2*96 + tid] = r2;
    cb[480 + tid] = sqrtf(r0*r0 + r1*r1 + r2*r2);
}

// =====================================================================
extern "C" void kernel_launch(void* const* d_in, const int* in_sizes, int n_in,
                              void* d_out, int out_size) {
    const float* act   = (const float*)d_in[0];
    const float* act2d = (const float*)d_in[1];
    const float* smask = (const float*)d_in[2];
    const float* rot   = (const float*)d_in[3];
    const float* trans = (const float*)d_in[4];
    const float* wq    = (const float*)d_in[5];
    const float* wk    = (const float*)d_in[6];
    const float* wv    = (const float*)d_in[7];
    const float* wqp   = (const float*)d_in[8];
    const float* bqp   = (const float*)d_in[9];
    const float* wkp   = (const float*)d_in[10];
    const float* bkp   = (const float*)d_in[11];
    const float* wvp   = (const float*)d_in[12];
    const float* bvp   = (const float*)d_in[13];
    const float* w2d   = (const float*)d_in[14];
    const float* b2d   = (const float*)d_in[15];
    const float* wfin  = (const float*)d_in[16];
    const float* bfin  = (const float*)d_in[17];
    const float* tw    = (const float*)d_in[18];
    float* out = (float*)d_out;

    float *p_wcat, *p_bcat, *p_proj, *p_cbuf;
    cudaGetSymbolAddress((void**)&p_wcat, g_wcat);
    cudaGetSymbolAddress((void**)&p_bcat, g_bcat);
    cudaGetSymbolAddress((void**)&p_proj, g_proj);
    cudaGetSymbolAddress((void**)&p_cbuf, g_cbuf);

    const int K2A_SMEM = 2*256*8*16 + 128*6*8;   // 71680 bytes
    cudaFuncSetAttribute(k2a, cudaFuncAttributeMaxDynamicSharedMemorySize, K2A_SMEM);

    kpack<<<(C1d*NPROJ + 255)/256, 256>>>(wq, wk, wv, wqp, bqp, wkp, bkp, wvp, bvp);
    gemm32<<<dim3(NN/32, NPROJ/64), 256>>>(act, p_wcat, p_bcat, p_proj, C1d, NPROJ);
    k1b<<<NN, 576>>>(rot, trans);
    k2a<<<NN*3, 128, K2A_SMEM>>>(act2d, w2d, b2d);
    k2b<<<dim3(4, 12, 12), 256>>>(smask, tw);
    k3_softmax<<<NN*HH, 256>>>();
    k4_r2d<<<NN, 256>>>(act2d);
    k5_av<<<dim3(24, 12), 256>>>();
    k5b_fin<<<NN, 96>>>(rot, trans);
    gemm32<<<dim3(NN/32, 384/64), 256>>>(p_cbuf, wfin, bfin, out, CONCAT, 384);
}

// round 16
// speedup vs baseline: 1.5385x; 1.0204x over previous
#include <cuda_runtime.h>
#include <math.h>

#define NN 768
#define HH 12
#define SQKd 16
#define SVd 16
#define PQKd 4
#define PVd 8
#define C1d 384
#define C2d 128
#define CONCAT 2112   // H*(SV + 4*PV + C2) = 12*176
#define NPROJ 1152    // 192*3 + 144*2 + 288

// -------- scratch (device globals; no allocation allowed) --------
__device__ __align__(16) float g_wcat[C1d*NPROJ];
__device__ __align__(16) float g_bcat[NPROJ];
__device__ __align__(16) float g_proj[NN*NPROJ];
__device__ __align__(16) float g_q  [NN*HH*SQKd];
__device__ __align__(16) float g_k  [NN*HH*SQKd];
__device__ __align__(16) float g_vh [HH*NN*SVd];
__device__ __align__(16) float g_qp [NN*HH*PQKd*3];
__device__ __align__(16) float g_kp [NN*HH*PQKd*3];
__device__ __align__(16) float g_vph[HH*NN*PVd*3];
__device__ __align__(16) float g_sq [NN*HH];
__device__ __align__(16) float g_sk [NN*HH];
__device__ __align__(16) float g_attn[(size_t)NN*HH*NN]; // [q][h][k]
__device__ __align__(16) float g_rpg[NN*HH*PVd*3];
__device__ __align__(16) float g_cbuf[NN*CONCAT];

// -------- f32x2 packed math helpers --------
typedef unsigned long long ull;
__device__ __forceinline__ ull pack2(float x, float y) {
    ull r; asm("mov.b64 %0, {%1, %2};" : "=l"(r) : "f"(x), "f"(y)); return r;
}
__device__ __forceinline__ float2 unpack2(ull v) {
    float2 r; asm("mov.b64 {%0, %1}, %2;" : "=f"(r.x), "=f"(r.y) : "l"(v)); return r;
}
__device__ __forceinline__ ull ffma2(ull a, ull b, ull c) {
    ull d; asm("fma.rn.f32x2 %0, %1, %2, %3;" : "=l"(d) : "l"(a), "l"(b), "l"(c)); return d;
}
__device__ __forceinline__ ull add2(ull a, ull b) {
    ull d; asm("add.rn.f32x2 %0, %1, %2;" : "=l"(d) : "l"(a), "l"(b)); return d;
}

// -------- cp.async helpers --------
__device__ __forceinline__ unsigned smem_u32(const void* p) {
    unsigned s;
    asm("{ .reg .u64 t; cvta.to.shared.u64 t, %1; cvt.u32.u64 %0, t; }"
        : "=r"(s) : "l"(p));
    return s;
}
__device__ __forceinline__ void cp_async16(void* dst_smem, const void* src_gmem) {
    asm volatile("cp.async.cg.shared.global [%0], [%1], 16;"
                 :: "r"(smem_u32(dst_smem)), "l"(src_gmem) : "memory");
}
__device__ __forceinline__ void cp_commit() {
    asm volatile("cp.async.commit_group;" ::: "memory");
}
template<int N>
__device__ __forceinline__ void cp_wait() {
    asm volatile("cp.async.wait_group %0;" :: "n"(N) : "memory");
}

// fast exp: 2^(x*log2e), range-reduced, degree-4 poly on FMA pipe.
__device__ __forceinline__ float fast_exp(float x) {
    float y = x * 1.44269504089f;
    y = fmaxf(y, -126.0f);
    float i = rintf(y);
    float f = y - i;
    float p = 0.00961804886f;
    p = fmaf(p, f, 0.05550410866f);
    p = fmaf(p, f, 0.24022650696f);
    p = fmaf(p, f, 0.69314718056f);
    p = fmaf(p, f, 1.0f);
    float s = __int_as_float(((int)i + 127) << 23);
    return p * s;
}

// =====================================================================
// KP: pack projection weights into one concat matrix [384 x 1152] + bias
// =====================================================================
__global__ void kpack(const float* __restrict__ wq, const float* __restrict__ wk,
                      const float* __restrict__ wv,
                      const float* __restrict__ wqp, const float* __restrict__ bqp,
                      const float* __restrict__ wkp, const float* __restrict__ bkp,
                      const float* __restrict__ wvp, const float* __restrict__ bvp) {
    int idx = blockIdx.x*256 + threadIdx.x;
    if (idx >= C1d*NPROJ) return;
    int c = idx / NPROJ, col = idx % NPROJ;
    float v;
    if (col < 192)      v = wq [c*192 + col];
    else if (col < 384) v = wk [c*192 + col-192];
    else if (col < 576) v = wv [c*192 + col-384];
    else if (col < 720) v = wqp[c*144 + col-576];
    else if (col < 864) v = wkp[c*144 + col-720];
    else                v = wvp[c*288 + col-864];
    g_wcat[idx] = v;
    if (c == 0) {
        float b = 0.f;
        if (col >= 576 && col < 720) b = bqp[col-576];
        else if (col >= 720 && col < 864) b = bkp[col-720];
        else if (col >= 864) b = bvp[col-864];
        g_bcat[col] = b;
    }
}

// =====================================================================
// gemm32: C[M,N] = A[M,K] @ B[K,N] + bias[N]. Tile 32m x 64n, kc=16.
// =====================================================================
__global__ void gemm32(const float* __restrict__ A, const float* __restrict__ B,
                       const float* __restrict__ bias, float* __restrict__ C,
                       int K, int N) {
    __shared__ float sAT[16][34];
    __shared__ float sB[16][68];
    int m0 = blockIdx.x * 32, n0 = blockIdx.y * 64;
    int tid = threadIdx.x;
    int tx = tid & 15, ty = tid >> 4;
    ull acc2[2][2];
    ull z = pack2(0.f, 0.f);
    acc2[0][0]=z; acc2[0][1]=z; acc2[1][0]=z; acc2[1][1]=z;

    for (int k0 = 0; k0 < K; k0 += 16) {
        if (tid < 128) {
            int row = tid >> 2, cp = (tid & 3) * 4;
            float4 a = *(const float4*)(A + (size_t)(m0+row)*K + k0 + cp);
            sAT[cp+0][row]=a.x; sAT[cp+1][row]=a.y; sAT[cp+2][row]=a.z; sAT[cp+3][row]=a.w;
        }
        {
            int r = tid >> 4, c = (tid & 15) * 4;
            float4 b = *(const float4*)(B + (size_t)(k0+r)*N + n0 + c);
            sB[r][c]=b.x; sB[r][c+1]=b.y; sB[r][c+2]=b.z; sB[r][c+3]=b.w;
        }
        __syncthreads();
        #pragma unroll
        for (int kk = 0; kk < 16; kk++) {
            float2 a = *(const float2*)&sAT[kk][ty*2];
            ull b20 = *(const ull*)&sB[kk][tx*4];
            ull b21 = *(const ull*)&sB[kk][tx*4+2];
            ull a20 = pack2(a.x, a.x), a21 = pack2(a.y, a.y);
            acc2[0][0] = ffma2(a20, b20, acc2[0][0]);
            acc2[0][1] = ffma2(a20, b21, acc2[0][1]);
            acc2[1][0] = ffma2(a21, b20, acc2[1][0]);
            acc2[1][1] = ffma2(a21, b21, acc2[1][1]);
        }
        __syncthreads();
    }
    #pragma unroll
    for (int i = 0; i < 2; i++) {
        float2 v0 = unpack2(acc2[i][0]);
        float2 v1 = unpack2(acc2[i][1]);
        float* dst = C + (size_t)(m0+ty*2+i)*N + n0 + tx*4;
        dst[0] = v0.x + bias[n0+tx*4+0];
        dst[1] = v0.y + bias[n0+tx*4+1];
        dst[2] = v1.x + bias[n0+tx*4+2];
        dst[3] = v1.y + bias[n0+tx*4+3];
    }
}

// =====================================================================
// K1b: scatter q/k/v, apply rigid frames to points, compute sq/sk.
// =====================================================================
__global__ void k1b(const float* __restrict__ rot, const float* __restrict__ trans) {
    int n = blockIdx.x;
    int tid = threadIdx.x; // 576
    __shared__ float s_p[NPROJ];
    __shared__ float s_app[96*3];
    __shared__ float s_rot[9], s_tr[3];
    for (int i = tid; i < NPROJ; i += 576) s_p[i] = g_proj[(size_t)n*NPROJ + i];
    if (tid < 9) s_rot[tid] = rot[n*9 + tid];
    if (tid < 3) s_tr[tid]  = trans[n*3 + tid];
    __syncthreads();

    if (tid < 192)      g_q[n*192 + tid] = s_p[tid] * 0.25f;
    else if (tid < 384) { int o = tid-192; g_k[n*192 + o] = s_p[192 + o]; }
    else { int o = tid-384; g_vh[(o >> 4)*(NN*SVd) + n*SVd + (o & 15)] = s_p[384 + o]; }

    const float* raw = s_p + 576;
    if (tid < 192) {
        float l0, l1, l2;
        if (tid < 48) {
            int h = tid >> 2, p = tid & 3;
            l0 = raw[h*12 + p]; l1 = raw[h*12 + 4 + p]; l2 = raw[h*12 + 8 + p];
        } else if (tid < 96) {
            int j = tid - 48; int h = j >> 2, p = j & 3;
            l0 = raw[144 + h*12 + p]; l1 = raw[144 + h*12 + 4 + p]; l2 = raw[144 + h*12 + 8 + p];
        } else {
            int j = tid - 96; int h = j >> 3, p = j & 7;
            l0 = raw[288 + h*24 + p]; l1 = raw[288 + h*24 + 8 + p]; l2 = raw[288 + h*24 + 16 + p];
        }
        float gx = s_rot[0]*l0 + s_rot[1]*l1 + s_rot[2]*l2 + s_tr[0];
        float gy = s_rot[3]*l0 + s_rot[4]*l1 + s_rot[5]*l2 + s_tr[1];
        float gz = s_rot[6]*l0 + s_rot[7]*l1 + s_rot[8]*l2 + s_tr[2];
        if (tid < 48) {
            g_qp[n*144 + tid*3+0] = gx; g_qp[n*144 + tid*3+1] = gy; g_qp[n*144 + tid*3+2] = gz;
            s_app[tid*3+0] = gx; s_app[tid*3+1] = gy; s_app[tid*3+2] = gz;
        } else if (tid < 96) {
            int j = tid - 48;
            g_kp[n*144 + j*3+0] = gx; g_kp[n*144 + j*3+1] = gy; g_kp[n*144 + j*3+2] = gz;
            s_app[tid*3+0] = gx; s_app[tid*3+1] = gy; s_app[tid*3+2] = gz;
        } else {
            int j = tid - 96; int h = j >> 3, p = j & 7;
            g_vph[h*(NN*PVd*3) + n*(PVd*3) + p*3+0] = gx;
            g_vph[h*(NN*PVd*3) + n*(PVd*3) + p*3+1] = gy;
            g_vph[h*(NN*PVd*3) + n*(PVd*3) + p*3+2] = gz;
        }
    }
    __syncthreads();
    if (tid < 24) {
        int h = tid % 12;
        int base = (tid < 12) ? 0 : 144;
        float s = 0.f;
        #pragma unroll
        for (int p = 0; p < 4; p++) {
            float x = s_app[base + (h*4+p)*3+0];
            float y = s_app[base + (h*4+p)*3+1];
            float z = s_app[base + (h*4+p)*3+2];
            s += x*x + y*y + z*z;
        }
        if (tid < 12) g_sq[n*12 + h] = s; else g_sk[n*12 + h] = s;
    }
}

// =====================================================================
// K2a v7 (proven 56.3us): Z = act2d @ w2d + b2d -> g_attn[q][h][k].
// cp.async double-buffered staging, XOR-swizzled float4 granules.
// =====================================================================
__global__ void __launch_bounds__(128) k2a(
        const float* __restrict__ act2d,
        const float* __restrict__ w2d,
        const float* __restrict__ b2d) {
    extern __shared__ char dynsm[];
    float4* s_a4 = (float4*)dynsm;                 // [2][256][8]
    ull*    s_w  = (ull*)(dynsm + 2*256*8*16);     // [128][6]
    int tid = threadIdx.x;  // 128
    int q = blockIdx.x / 3, k0 = (blockIdx.x % 3) * 256;

    for (int i = tid; i < 768; i += 128) {
        int c = i / 6, hh = i % 6;
        s_w[i] = pack2(w2d[c*12 + hh*2], w2d[c*12 + hh*2 + 1]);
    }
    ull acc[2][6];
    #pragma unroll
    for (int hh = 0; hh < 6; hh++) {
        ull b = pack2(b2d[2*hh], b2d[2*hh+1]);
        acc[0][hh] = b; acc[1][hh] = b;
    }

    const float* base = act2d + ((size_t)q*NN + k0)*C2d;

    #pragma unroll
    for (int it = 0; it < 16; it++) {
        int i = it*128 + tid;
        int r = i >> 3, c4 = i & 7;
        cp_async16(s_a4 + (size_t)r*8 + (c4 ^ (r&7)),
                   base + (size_t)r*C2d + c4*4);
    }
    cp_commit();

    #pragma unroll
    for (int ch = 0; ch < 4; ch++) {
        int buf = ch & 1;
        if (ch < 3) {
            int c0n = (ch+1)*32;
            #pragma unroll
            for (int it = 0; it < 16; it++) {
                int i = it*128 + tid;
                int r = i >> 3, c4 = i & 7;
                cp_async16(s_a4 + ((size_t)(buf^1)*256 + r)*8 + (c4 ^ (r&7)),
                           base + (size_t)r*C2d + c0n + c4*4);
            }
            cp_commit();
            cp_wait<1>();
        } else {
            cp_wait<0>();
        }
        __syncthreads();

        int c0 = ch*32;
        #pragma unroll
        for (int g4 = 0; g4 < 8; g4++) {
            int pos = g4 ^ (tid & 7);
            float4 a0 = s_a4[((size_t)buf*256 + tid)*8 + pos];
            float4 a1 = s_a4[((size_t)buf*256 + tid + 128)*8 + pos];
            float av0[4] = {a0.x, a0.y, a0.z, a0.w};
            float av1[4] = {a1.x, a1.y, a1.z, a1.w};
            #pragma unroll
            for (int u = 0; u < 4; u++) {
                const ull* wr = s_w + (size_t)(c0 + g4*4 + u)*6;
                ulonglong2 w01 = *(const ulonglong2*)(wr);
                ulonglong2 w23 = *(const ulonglong2*)(wr+2);
                ulonglong2 w45 = *(const ulonglong2*)(wr+4);
                ull p0 = pack2(av0[u], av0[u]);
                ull p1 = pack2(av1[u], av1[u]);
                acc[0][0] = ffma2(p0, w01.x, acc[0][0]);
                acc[0][1] = ffma2(p0, w01.y, acc[0][1]);
                acc[0][2] = ffma2(p0, w23.x, acc[0][2]);
                acc[0][3] = ffma2(p0, w23.y, acc[0][3]);
                acc[0][4] = ffma2(p0, w45.x, acc[0][4]);
                acc[0][5] = ffma2(p0, w45.y, acc[0][5]);
                acc[1][0] = ffma2(p1, w01.x, acc[1][0]);
                acc[1][1] = ffma2(p1, w01.y, acc[1][1]);
                acc[1][2] = ffma2(p1, w23.x, acc[1][2]);
                acc[1][3] = ffma2(p1, w23.y, acc[1][3]);
                acc[1][4] = ffma2(p1, w45.x, acc[1][4]);
                acc[1][5] = ffma2(p1, w45.y, acc[1][5]);
            }
        }
        __syncthreads();
    }
    #pragma unroll
    for (int kk = 0; kk < 2; kk++) {
        float* dst = g_attn + (size_t)q*(HH*NN) + k0 + kk*128 + tid;
        #pragma unroll
        for (int hh = 0; hh < 6; hh++) {
            float2 v = unpack2(acc[kk][hh]);
            dst[(size_t)(2*hh)*NN]   = v.x;
            dst[(size_t)(2*hh+1)*NN] = v.y;
        }
    }
}

// =====================================================================
// K2b: add qk-dot + point-distance + mask terms, scale. Per head.
// =====================================================================
__global__ void k2b(const float* __restrict__ smask, const float* __restrict__ tw) {
    int k0 = blockIdx.x * 192, q0 = blockIdx.y * 64, h = blockIdx.z;
    int tid = threadIdx.x;
    __shared__ float s_qc[64][28];
    __shared__ float s_kc[28][192];
    __shared__ float s_sq[64], s_sk[192], s_mq[64], s_mk[192];
    float pw = 0.23570226039f * log1pf(expf(tw[h]));

    for (int i = tid; i < 64*16;  i += 256) { int r=i>>4, c=i&15;  s_qc[r][c]    = g_q [(q0+r)*192 + h*16 + c]; }
    for (int i = tid; i < 64*12;  i += 256) { int r=i/12, c=i%12;  s_qc[r][16+c] = pw * g_qp[(q0+r)*144 + h*12 + c]; }
    for (int i = tid; i < 192*16; i += 256) { int kk=i>>4, c=i&15; s_kc[c][kk]    = g_k [(k0+kk)*192 + h*16 + c]; }
    for (int i = tid; i < 192*12; i += 256) { int kk=i/12, c=i%12; s_kc[16+c][kk] = g_kp[(k0+kk)*144 + h*12 + c]; }
    if (tid < 64)  { s_sq[tid] = g_sq[(q0+tid)*12 + h]; s_mq[tid] = smask[q0+tid]; }
    if (tid < 192) { s_sk[tid] = g_sk[(k0+tid)*12 + h]; s_mk[tid] = smask[k0+tid]; }
    __syncthreads();

    int tc = tid & 31, tr = tid >> 5;
    ull acc2[8][3];
    ull z = pack2(0.f, 0.f);
    #pragma unroll
    for (int i = 0; i < 8; i++) { acc2[i][0]=z; acc2[i][1]=z; acc2[i][2]=z; }

    #pragma unroll 4
    for (int c = 0; c < 28; c++) {
        const float* kr = &s_kc[c][tc];
        ull b2[3];
        #pragma unroll
        for (int jp = 0; jp < 3; jp++) b2[jp] = pack2(kr[32*(2*jp)], kr[32*(2*jp+1)]);
        #pragma unroll
        for (int i = 0; i < 8; i++) {
            float a = s_qc[tr*8+i][c];
            ull a2 = pack2(a, a);
            acc2[i][0] = ffma2(a2, b2[0], acc2[i][0]);
            acc2[i][1] = ffma2(a2, b2[1], acc2[i][1]);
            acc2[i][2] = ffma2(a2, b2[2], acc2[i][2]);
        }
    }
    #pragma unroll
    for (int i = 0; i < 8; i++) {
        int q = q0 + tr*8 + i;
        float sqv = s_sq[tr*8+i], mq = s_mq[tr*8+i];
        float* row = g_attn + (size_t)q*(HH*NN) + h*NN + k0 + tc;
        #pragma unroll
        for (int jp = 0; jp < 3; jp++) {
            float2 v = unpack2(acc2[i][jp]);
            int j0 = 32*(2*jp), j1 = 32*(2*jp+1);
            float l0 = row[j0] + v.x - 0.5f*pw*(sqv + s_sk[tc+j0]) - 1e5f*(1.f - mq*s_mk[tc+j0]);
            float l1 = row[j1] + v.y - 0.5f*pw*(sqv + s_sk[tc+j1]) - 1e5f*(1.f - mq*s_mk[tc+j1]);
            row[j0] = l0 * 0.57735026919f;
            row[j1] = l1 * 0.57735026919f;
        }
    }
}

// =====================================================================
// K3: softmax over keys. 9216 rows of 768, poly exp on FMA pipe.
// =====================================================================
__global__ void k3_softmax() {
    int r = blockIdx.x;
    float* row = g_attn + (size_t)r*NN;
    int tid = threadIdx.x;
    float v0 = row[tid], v1 = row[tid+256], v2 = row[tid+512];
    float m = fmaxf(fmaxf(v0, v1), v2);
    __shared__ float sred[8];
    #pragma unroll
    for (int o = 16; o; o >>= 1) m = fmaxf(m, __shfl_xor_sync(0xffffffffu, m, o));
    if ((tid & 31) == 0) sred[tid >> 5] = m;
    __syncthreads();
    float mm = sred[0];
    #pragma unroll
    for (int i = 1; i < 8; i++) mm = fmaxf(mm, sred[i]);
    float e0 = fast_exp(v0 - mm), e1 = fast_exp(v1 - mm), e2 = fast_exp(v2 - mm);
    float s = e0 + e1 + e2;
    #pragma unroll
    for (int o = 16; o; o >>= 1) s += __shfl_xor_sync(0xffffffffu, s, o);
    __syncthreads();
    if ((tid & 31) == 0) sred[tid >> 5] = s;
    __syncthreads();
    float ss = 0.f;
    #pragma unroll
    for (int i = 0; i < 8; i++) ss += sred[i];
    float rc = 1.f / ss;
    row[tid] = e0*rc; row[tid+256] = e1*rc; row[tid+512] = e2*rc;
}

// =====================================================================
// K4 v4: r2d = attn @ act_2d, cp.async double-buffered.
// Block = one q, 256 threads. j streamed in 24 chunks of 32 rows.
// Stage [2][32][32] float4 (32KB) + s_at attn [768][12] (36.9KB).
// Lane g owns 4 channels; warp p owns rows p*4..p*4+3 of each chunk.
// Act reads: warp-wide one-row sweep (conflict-free). Weights: LDS.128
// broadcast. Final 8-part reduction via smem overlay (unchanged).
// =====================================================================
__global__ void k4_r2d(const float* __restrict__ act2d) {
    extern __shared__ char dynsm4[];
    float4* s_st = (float4*)dynsm4;                   // [2][32][32]
    float*  s_at = (float*)(dynsm4 + 2*32*32*16);     // [768][12]
    int q = blockIdx.x;
    int tid = threadIdx.x; // 256

    for (int i = tid; i < NN*HH; i += 256) {
        int h = i / NN, j = i % NN;
        s_at[j*12 + h] = g_attn[(size_t)q*(HH*NN) + i];
    }

    int g = tid & 31;   // channel group: channels g*4..g*4+3
    int p = tid >> 5;   // row sub-part within chunk
    ull acc[4][6];
    ull z = pack2(0.f, 0.f);
    #pragma unroll
    for (int c = 0; c < 4; c++)
        #pragma unroll
        for (int hh = 0; hh < 6; hh++) acc[c][hh] = z;

    const float* base = act2d + (size_t)q*NN*C2d;

    // prologue: stage chunk 0 (rows 0..31) into buf 0
    #pragma unroll
    for (int it = 0; it < 4; it++) {
        int i = it*256 + tid;
        int r = i >> 5, c4 = i & 31;
        cp_async16(s_st + (size_t)r*32 + c4, base + (size_t)r*C2d + c4*4);
    }
    cp_commit();

    for (int chunk = 0; chunk < 24; chunk++) {
        int buf = chunk & 1;
        if (chunk < 23) {
            int r0 = (chunk+1)*32;
            #pragma unroll
            for (int it = 0; it < 4; it++) {
                int i = it*256 + tid;
                int r = i >> 5, c4 = i & 31;
                cp_async16(s_st + ((size_t)(buf^1)*32 + r)*32 + c4,
                           base + (size_t)(r0+r)*C2d + c4*4);
            }
            cp_commit();
            cp_wait<1>();
        } else {
            cp_wait<0>();
        }
        __syncthreads();   // staged data + (first iter) s_at visible

        #pragma unroll
        for (int js = 0; js < 4; js++) {
            int jl = p*4 + js;                       // row within chunk
            float4 a = s_st[((size_t)buf*32 + jl)*32 + g];
            const ull* w = (const ull*)(s_at + (chunk*32 + jl)*12);
            ulonglong2 w01 = *(const ulonglong2*)(w);
            ulonglong2 w23 = *(const ulonglong2*)(w+2);
            ulonglong2 w45 = *(const ulonglong2*)(w+4);
            float av[4] = {a.x, a.y, a.z, a.w};
            #pragma unroll
            for (int c = 0; c < 4; c++) {
                ull a2 = pack2(av[c], av[c]);
                acc[c][0] = ffma2(a2, w01.x, acc[c][0]);
                acc[c][1] = ffma2(a2, w01.y, acc[c][1]);
                acc[c][2] = ffma2(a2, w23.x, acc[c][2]);
                acc[c][3] = ffma2(a2, w23.y, acc[c][3]);
                acc[c][4] = ffma2(a2, w45.x, acc[c][4]);
                acc[c][5] = ffma2(a2, w45.y, acc[c][5]);
            }
        }
        __syncthreads();
    }

    // reduce across the 8 parts, one channel-within-group per round
    ull* rb = (ull*)s_at;
    float* cb = g_cbuf + (size_t)q*CONCAT + 576;
    #pragma unroll
    for (int c = 0; c < 4; c++) {
        __syncthreads();
        #pragma unroll
        for (int hh = 0; hh < 6; hh++) rb[p*192 + g*6 + hh] = acc[c][hh];
        __syncthreads();
        if (tid < 192) {
            ull s = rb[tid];
            #pragma unroll
            for (int p2 = 1; p2 < 8; p2++) s = add2(s, rb[p2*192 + tid]);
            int g2 = tid / 6, hh = tid % 6;
            float2 v = unpack2(s);
            int ch = g2*4 + c;
            cb[(2*hh)*128 + ch]   = v.x;
            cb[(2*hh+1)*128 + ch] = v.y;
        }
    }
}

// =====================================================================
// K5 v2: attn @ [v | vp] per head. 32-q tiles -> 288 blocks.
// =====================================================================
__global__ void k5_av() {
    __shared__ float sA[32][65];
    __shared__ float sB[64][40];
    int h = blockIdx.y;
    int q0 = blockIdx.x * 32;
    int tid = threadIdx.x;   // 256
    int tc = tid & 7, tr = tid >> 3;
    float acc[5] = {0.f, 0.f, 0.f, 0.f, 0.f};

    for (int k0 = 0; k0 < NN; k0 += 64) {
        for (int i = tid; i < 512; i += 256) {
            int r = i >> 4, c4 = i & 15;
            float4 v = *(const float4*)(g_attn + (size_t)(q0+r)*(HH*NN) + h*NN + k0 + c4*4);
            sA[r][c4*4+0] = v.x; sA[r][c4*4+1] = v.y; sA[r][c4*4+2] = v.z; sA[r][c4*4+3] = v.w;
        }
        for (int i = tid; i < 64*40; i += 256) {
            int kk = i / 40, c = i % 40;
            sB[kk][c] = (c < 16)
                ? g_vh [h*(NN*SVd)   + (k0+kk)*SVd   + c]
                : g_vph[h*(NN*PVd*3) + (k0+kk)*PVd*3 + (c-16)];
        }
        __syncthreads();
        #pragma unroll 8
        for (int kk = 0; kk < 64; kk++) {
            float a = sA[tr][kk];
            float b[5];
            #pragma unroll
            for (int j = 0; j < 5; j++) b[j] = sB[kk][tc*5+j];
            #pragma unroll
            for (int j = 0; j < 5; j++) acc[j] += a*b[j];
        }
        __syncthreads();
    }
    int q = q0 + tr;
    #pragma unroll
    for (int j = 0; j < 5; j++) {
        int c = tc*5 + j;
        if (c < 16) g_cbuf[q*CONCAT + h*16 + c] = acc[j];
        else        g_rpg [q*(HH*PVd*3) + h*(PVd*3) + (c-16)] = acc[j];
    }
}

// =====================================================================
// K5b: invert frames + norms.
// =====================================================================
__global__ void k5b_fin(const float* __restrict__ rot,
                        const float* __restrict__ trans) {
    int q = blockIdx.x;
    int tid = threadIdx.x; // 96
    float t0 = g_rpg[q*288 + tid*3+0] - trans[q*3+0];
    float t1 = g_rpg[q*288 + tid*3+1] - trans[q*3+1];
    float t2 = g_rpg[q*288 + tid*3+2] - trans[q*3+2];
    const float* R = rot + q*9;
    float r0 = R[0]*t0 + R[3]*t1 + R[6]*t2;
    float r1 = R[1]*t0 + R[4]*t1 + R[7]*t2;
    float r2 = R[2]*t0 + R[5]*t1 + R[8]*t2;
    float* cb = g_cbuf + q*CONCAT;
    cb[192 + 0*96 + tid] = r0;
    cb[192 + 1*96 + tid] = r1;
    cb[192 + 2*96 + tid] = r2;
    cb[480 + tid] = sqrtf(r0*r0 + r1*r1 + r2*r2);
}

// =====================================================================
extern "C" void kernel_launch(void* const* d_in, const int* in_sizes, int n_in,
                              void* d_out, int out_size) {
    const float* act   = (const float*)d_in[0];
    const float* act2d = (const float*)d_in[1];
    const float* smask = (const float*)d_in[2];
    const float* rot   = (const float*)d_in[3];
    const float* trans = (const float*)d_in[4];
    const float* wq    = (const float*)d_in[5];
    const float* wk    = (const float*)d_in[6];
    const float* wv    = (const float*)d_in[7];
    const float* wqp   = (const float*)d_in[8];
    const float* bqp   = (const float*)d_in[9];
    const float* wkp   = (const float*)d_in[10];
    const float* bkp   = (const float*)d_in[11];
    const float* wvp   = (const float*)d_in[12];
    const float* bvp   = (const float*)d_in[13];
    const float* w2d   = (const float*)d_in[14];
    const float* b2d   = (const float*)d_in[15];
    const float* wfin  = (const float*)d_in[16];
    const float* bfin  = (const float*)d_in[17];
    const float* tw    = (const float*)d_in[18];
    float* out = (float*)d_out;

    float *p_wcat, *p_bcat, *p_proj, *p_cbuf;
    cudaGetSymbolAddress((void**)&p_wcat, g_wcat);
    cudaGetSymbolAddress((void**)&p_bcat, g_bcat);
    cudaGetSymbolAddress((void**)&p_proj, g_proj);
    cudaGetSymbolAddress((void**)&p_cbuf, g_cbuf);

    const int K2A_SMEM = 2*256*8*16 + 128*6*8;   // 71680 bytes
    cudaFuncSetAttribute(k2a, cudaFuncAttributeMaxDynamicSharedMemorySize, K2A_SMEM);
    const int K4_SMEM = 2*32*32*16 + NN*HH*4;    // 32768 + 36864 = 69632
    cudaFuncSetAttribute(k4_r2d, cudaFuncAttributeMaxDynamicSharedMemorySize, K4_SMEM);

    kpack<<<(C1d*NPROJ + 255)/256, 256>>>(wq, wk, wv, wqp, bqp, wkp, bkp, wvp, bvp);
    gemm32<<<dim3(NN/32, NPROJ/64), 256>>>(act, p_wcat, p_bcat, p_proj, C1d, NPROJ);
    k1b<<<NN, 576>>>(rot, trans);
    k2a<<<NN*3, 128, K2A_SMEM>>>(act2d, w2d, b2d);
    k2b<<<dim3(4, 12, 12), 256>>>(smask, tw);
    k3_softmax<<<NN*HH, 256>>>();
    k4_r2d<<<NN, 256, K4_SMEM>>>(act2d);
    k5_av<<<dim3(24, 12), 256>>>();
    k5b_fin<<<NN, 96>>>(rot, trans);
    gemm32<<<dim3(NN/32, 384/64), 256>>>(p_cbuf, wfin, bfin, out, CONCAT, 384);
}